// round 1
// baseline (speedup 1.0000x reference)
#include <cuda_runtime.h>
#include <cuda_bf16.h>
#include <cstdint>

// Problem constants
#define B_  4
#define T_  2048
#define C_  1024
#define H_  16
#define D_  64
#define M_  (B_ * T_)      // 8192 rows
#define NK_ 1024           // N = K = 1024 for all gemms

// Scratch (device globals: allowed by harness rules)
__device__ float g_Q[(size_t)B_ * H_ * T_ * D_];   // [B,H,T,D]
__device__ float g_K[(size_t)B_ * H_ * T_ * D_];
__device__ float g_V[(size_t)B_ * H_ * T_ * D_];
__device__ float g_Y[(size_t)M_ * C_];             // [B,T,C]

// ---------------------------------------------------------------------------
// SGEMM-NT: out[m][n] = sum_k A[m][k] * W[n][k]  (+bias)
// A: [8192,1024] row-major, W: [1024,1024] row-major.
// mode 0: plain write      mode 1: permuted write into [B,H,T,D]
// mode 2: plain + bias
// a_sel: -1 -> A_ext, 3 -> g_Y     out_sel: -1 -> out_ext, 0/1/2 -> g_Q/K/V
// ---------------------------------------------------------------------------
__global__ __launch_bounds__(256)
void sgemm_nt(const float* __restrict__ A_ext, int a_sel,
              const float* __restrict__ W,
              float* __restrict__ out_ext, int out_sel,
              const float* __restrict__ bias, int mode)
{
    const int K = NK_, N = NK_;
    const float* A = (a_sel < 0) ? A_ext : g_Y;
    float* OUT;
    if (out_sel < 0)      OUT = out_ext;
    else if (out_sel == 0) OUT = g_Q;
    else if (out_sel == 1) OUT = g_K;
    else                   OUT = g_V;

    __shared__ float As[16][132];
    __shared__ float Bs[16][132];

    const int tid = threadIdx.x;
    const int bm = blockIdx.y, bn = blockIdx.x;
    const int tx = tid & 15, ty = tid >> 4;

    float acc[8][8];
#pragma unroll
    for (int i = 0; i < 8; i++)
#pragma unroll
        for (int j = 0; j < 8; j++) acc[i][j] = 0.f;

    const float* Aptr = A + (size_t)(bm * 128) * K;
    const float* Bptr = W + (size_t)(bn * 128) * K;

    for (int kb = 0; kb < K; kb += 16) {
#pragma unroll
        for (int u = 0; u < 2; u++) {
            int f = tid + u * 256;
            int r = f >> 2, kq = (f & 3) * 4;
            float4 a = *(const float4*)(Aptr + (size_t)r * K + kb + kq);
            As[kq + 0][r] = a.x; As[kq + 1][r] = a.y;
            As[kq + 2][r] = a.z; As[kq + 3][r] = a.w;
            float4 b = *(const float4*)(Bptr + (size_t)r * K + kb + kq);
            Bs[kq + 0][r] = b.x; Bs[kq + 1][r] = b.y;
            Bs[kq + 2][r] = b.z; Bs[kq + 3][r] = b.w;
        }
        __syncthreads();
#pragma unroll
        for (int k = 0; k < 16; k++) {
            float a[8], b[8];
#pragma unroll
            for (int i = 0; i < 8; i++) a[i] = As[k][ty * 8 + i];
#pragma unroll
            for (int j = 0; j < 8; j++) b[j] = Bs[k][tx * 8 + j];
#pragma unroll
            for (int i = 0; i < 8; i++)
#pragma unroll
                for (int j = 0; j < 8; j++)
                    acc[i][j] += a[i] * b[j];
        }
        __syncthreads();
    }

    // Epilogue
    const int nbase = bn * 128 + tx * 8;
    if (mode == 1) {
        // permuted: out[((b*H + h)*T + t)*D + d]
        const int h = nbase >> 6, d = nbase & 63;
#pragma unroll
        for (int i = 0; i < 8; i++) {
            int m = bm * 128 + ty * 8 + i;
            int bidx = m >> 11, t = m & 2047;
            float* dst = ((out_sel == 0) ? g_Q : (out_sel == 1) ? g_K : g_V)
                         + (((size_t)bidx * H_ + h) * T_ + t) * D_ + d;
            float4 v0 = { acc[i][0], acc[i][1], acc[i][2], acc[i][3] };
            float4 v1 = { acc[i][4], acc[i][5], acc[i][6], acc[i][7] };
            *(float4*)(dst)     = v0;
            *(float4*)(dst + 4) = v1;
        }
    } else {
        float bv[8];
#pragma unroll
        for (int j = 0; j < 8; j++) bv[j] = (mode == 2) ? bias[nbase + j] : 0.f;
#pragma unroll
        for (int i = 0; i < 8; i++) {
            int m = bm * 128 + ty * 8 + i;
            float* dst = OUT + (size_t)m * N + nbase;
            float4 v0 = { acc[i][0] + bv[0], acc[i][1] + bv[1],
                          acc[i][2] + bv[2], acc[i][3] + bv[3] };
            float4 v1 = { acc[i][4] + bv[4], acc[i][5] + bv[5],
                          acc[i][6] + bv[6], acc[i][7] + bv[7] };
            *(float4*)(dst)     = v0;
            *(float4*)(dst + 4) = v1;
        }
    }
}

// ---------------------------------------------------------------------------
// Flash-attention (fp32, causal). One block = 64 queries of one (b,h).
// Smem: Qs[64][68], Ks[64][68] (reused for P), Vs[64][68], m/l/alpha[64].
// ---------------------------------------------------------------------------
#define ATT_PAD   68
#define ATT_SMEMF (3 * 64 * ATT_PAD + 192)
#define ATT_SMEMB (ATT_SMEMF * 4)

__global__ __launch_bounds__(256)
void attn_kernel(void)
{
    extern __shared__ float sm[];
    float* Qs   = sm;
    float* Ks   = sm + 64 * ATT_PAD;     // reused as P after S is computed
    float* Vs   = sm + 2 * 64 * ATT_PAD;
    float* mrow = sm + 3 * 64 * ATT_PAD;
    float* lrow = mrow + 64;
    float* arow = lrow + 64;

    const int tid = threadIdx.x;
    const int qt = blockIdx.x;         // query tile (0..31)
    const int bh = blockIdx.y;         // b*H + h   (0..63)
    const int tx = tid & 15, ty = tid >> 4;
    const int r0 = ty * 4, c0 = tx * 4;

    // Load Q tile [64,64]
    const float* Qb = g_Q + ((size_t)bh * T_ + qt * 64) * D_;
#pragma unroll
    for (int u = 0; u < 4; u++) {
        int f = tid + u * 256;
        int r = f >> 4, d = (f & 15) * 4;
        *(float4*)(Qs + r * ATT_PAD + d) = *(const float4*)(Qb + r * D_ + d);
    }
    if (tid < 64) { mrow[tid] = -1e30f; lrow[tid] = 0.f; }

    float o[4][4];
#pragma unroll
    for (int i = 0; i < 4; i++)
#pragma unroll
        for (int j = 0; j < 4; j++) o[i][j] = 0.f;

    for (int kt = 0; kt <= qt; kt++) {
        __syncthreads();   // previous iteration done with Ks(P)/Vs
        const float* Kb = g_K + ((size_t)bh * T_ + kt * 64) * D_;
        const float* Vb = g_V + ((size_t)bh * T_ + kt * 64) * D_;
#pragma unroll
        for (int u = 0; u < 4; u++) {
            int f = tid + u * 256;
            int r = f >> 4, d = (f & 15) * 4;
            *(float4*)(Ks + r * ATT_PAD + d) = *(const float4*)(Kb + r * D_ + d);
            *(float4*)(Vs + r * ATT_PAD + d) = *(const float4*)(Vb + r * D_ + d);
        }
        __syncthreads();

        // S = Q K^T  (4x4 per thread)
        float s[4][4];
#pragma unroll
        for (int i = 0; i < 4; i++)
#pragma unroll
            for (int j = 0; j < 4; j++) s[i][j] = 0.f;

#pragma unroll
        for (int d = 0; d < 64; d += 4) {
            float qa[4][4], kb[4][4];
#pragma unroll
            for (int i = 0; i < 4; i++) {
                float4 t = *(const float4*)(Qs + (r0 + i) * ATT_PAD + d);
                qa[i][0] = t.x; qa[i][1] = t.y; qa[i][2] = t.z; qa[i][3] = t.w;
            }
#pragma unroll
            for (int j = 0; j < 4; j++) {
                float4 t = *(const float4*)(Ks + (c0 + j) * ATT_PAD + d);
                kb[j][0] = t.x; kb[j][1] = t.y; kb[j][2] = t.z; kb[j][3] = t.w;
            }
#pragma unroll
            for (int i = 0; i < 4; i++)
#pragma unroll
                for (int j = 0; j < 4; j++)
#pragma unroll
                    for (int e = 0; e < 4; e++)
                        s[i][j] += qa[i][e] * kb[j][e];
        }

        // scale + causal mask
        const float scale = 0.125f;  // 1/sqrt(64)
        if (kt == qt) {
#pragma unroll
            for (int i = 0; i < 4; i++)
#pragma unroll
                for (int j = 0; j < 4; j++)
                    s[i][j] = ((c0 + j) <= (r0 + i)) ? s[i][j] * scale : -1e30f;
        } else {
#pragma unroll
            for (int i = 0; i < 4; i++)
#pragma unroll
                for (int j = 0; j < 4; j++) s[i][j] *= scale;
        }

        __syncthreads();   // all S reads of Ks done -> reuse as P
#pragma unroll
        for (int i = 0; i < 4; i++) {
            float4 v = { s[i][0], s[i][1], s[i][2], s[i][3] };
            *(float4*)(Ks + (r0 + i) * ATT_PAD + c0) = v;
        }
        __syncthreads();

        // Online softmax stats: 4 threads per row
        {
            int r = tid >> 2, q = tid & 3;
            float* Pr = Ks + r * ATT_PAD + q * 16;
            float pm = -1e30f;
#pragma unroll
            for (int c = 0; c < 16; c++) pm = fmaxf(pm, Pr[c]);
            pm = fmaxf(pm, __shfl_xor_sync(0xffffffffu, pm, 1));
            pm = fmaxf(pm, __shfl_xor_sync(0xffffffffu, pm, 2));
            float om = mrow[r];
            float nm = fmaxf(om, pm);
            float al = __expf(om - nm);
            float ps = 0.f;
#pragma unroll
            for (int c = 0; c < 16; c++) {
                float p = __expf(Pr[c] - nm);
                Pr[c] = p;
                ps += p;
            }
            ps += __shfl_xor_sync(0xffffffffu, ps, 1);
            ps += __shfl_xor_sync(0xffffffffu, ps, 2);
            if (q == 0) { lrow[r] = lrow[r] * al + ps; mrow[r] = nm; arow[r] = al; }
        }
        __syncthreads();

        // Rescale O, then O += P V
#pragma unroll
        for (int i = 0; i < 4; i++) {
            float al = arow[r0 + i];
#pragma unroll
            for (int j = 0; j < 4; j++) o[i][j] *= al;
        }
#pragma unroll
        for (int s4 = 0; s4 < 64; s4 += 4) {
            float pa[4][4], vv[4][4];
#pragma unroll
            for (int i = 0; i < 4; i++) {
                float4 t = *(const float4*)(Ks + (r0 + i) * ATT_PAD + s4);
                pa[i][0] = t.x; pa[i][1] = t.y; pa[i][2] = t.z; pa[i][3] = t.w;
            }
#pragma unroll
            for (int ss = 0; ss < 4; ss++) {
                float4 t = *(const float4*)(Vs + (s4 + ss) * ATT_PAD + c0);
                vv[ss][0] = t.x; vv[ss][1] = t.y; vv[ss][2] = t.z; vv[ss][3] = t.w;
            }
#pragma unroll
            for (int i = 0; i < 4; i++)
#pragma unroll
                for (int j = 0; j < 4; j++)
#pragma unroll
                    for (int e = 0; e < 4; e++)
                        o[i][j] += pa[i][e] * vv[e][j];
        }
    }

    // Epilogue: normalize and write [B,T,C]
    const int b = bh >> 4, h = bh & 15;
#pragma unroll
    for (int i = 0; i < 4; i++) {
        float inv = 1.f / lrow[r0 + i];
        int t = qt * 64 + r0 + i;
        float4 v = { o[i][0] * inv, o[i][1] * inv, o[i][2] * inv, o[i][3] * inv };
        *(float4*)(g_Y + ((size_t)b * T_ + t) * C_ + h * D_ + c0) = v;
    }
}

// ---------------------------------------------------------------------------
extern "C" void kernel_launch(void* const* d_in, const int* in_sizes, int n_in,
                              void* d_out, int out_size)
{
    const float* X  = (const float*)d_in[0];
    const float* Wq = (const float*)d_in[1];
    const float* Wk = (const float*)d_in[2];
    const float* Wv = (const float*)d_in[3];
    const float* Wo = (const float*)d_in[4];
    const float* bo = (const float*)d_in[5];
    float* out = (float*)d_out;

    dim3 ggrid(NK_ / 128, M_ / 128);   // (8, 64)

    // QKV projections -> [B,H,T,D] scratch
    sgemm_nt<<<ggrid, 256>>>(X, -1, Wq, nullptr, 0, nullptr, 1);
    sgemm_nt<<<ggrid, 256>>>(X, -1, Wk, nullptr, 1, nullptr, 1);
    sgemm_nt<<<ggrid, 256>>>(X, -1, Wv, nullptr, 2, nullptr, 1);

    // Attention -> g_Y [B,T,C]
    cudaFuncSetAttribute(attn_kernel,
                         cudaFuncAttributeMaxDynamicSharedMemorySize, ATT_SMEMB);
    attn_kernel<<<dim3(T_ / 64, B_ * H_), 256, ATT_SMEMB>>>();

    // Output projection + bias -> d_out
    sgemm_nt<<<ggrid, 256>>>(nullptr, 3, Wo, out, -1, bo, 2);
}

// round 3
// speedup vs baseline: 3.7212x; 3.7212x over previous
#include <cuda_runtime.h>
#include <cuda_bf16.h>
#include <cstdint>

#define B_  4
#define T_  2048
#define C_  1024
#define H_  16
#define D_  64
#define M_  (B_ * T_)
#define NK_ 1024

__device__ float g_Q[(size_t)B_ * H_ * T_ * D_];
__device__ float g_K[(size_t)B_ * H_ * T_ * D_];
__device__ float g_V[(size_t)B_ * H_ * T_ * D_];
__device__ float g_Y[(size_t)M_ * C_];

__device__ __forceinline__ float to_tf32(float x) {
    uint32_t u;
    asm("cvt.rna.tf32.f32 %0, %1;" : "=r"(u) : "f"(x));
    return __uint_as_float(u);
}

__device__ __forceinline__ void mma_tf32(float c[4], const uint32_t a[4], const uint32_t b[2]) {
    asm volatile(
        "mma.sync.aligned.m16n8k8.row.col.f32.tf32.tf32.f32 "
        "{%0,%1,%2,%3}, {%4,%5,%6,%7}, {%8,%9}, {%0,%1,%2,%3};"
        : "+f"(c[0]), "+f"(c[1]), "+f"(c[2]), "+f"(c[3])
        : "r"(a[0]), "r"(a[1]), "r"(a[2]), "r"(a[3]), "r"(b[0]), "r"(b[1]));
}

// ---------------------------------------------------------------------------
// TF32 SGEMM-NT: out[m][n] = sum_k A[m][k] * W[n][k]  (+bias)
// Block 128x128, warp 32x64, BK=16, double-buffered smem.
// ---------------------------------------------------------------------------
#define BK   16
#define PADG 20
#define GEMM_SMEM (2 * 128 * PADG * 2 * 4)   // 40960 B

__global__ __launch_bounds__(256, 2)
void gemm_tf32(const float* __restrict__ A_ext, int a_sel,
               const float* __restrict__ W,
               float* __restrict__ out_ext, int out_sel,
               const float* __restrict__ bias, int mode)
{
    extern __shared__ float sm[];
    float* Asm = sm;                       // [2][128*PADG]
    float* Bsm = sm + 2 * 128 * PADG;      // [2][128*PADG]

    const float* A = (a_sel < 0) ? A_ext : g_Y;
    float* OUT = (out_sel < 0) ? out_ext
               : (out_sel == 0 ? g_Q : (out_sel == 1 ? g_K : g_V));

    const int tid  = threadIdx.x;
    const int lane = tid & 31, wid = tid >> 5;
    const int wm = (wid >> 1) * 32;        // warp row block (4)
    const int wn = (wid & 1) * 64;         // warp col block (2)
    const int r = lane >> 2, cq = lane & 3;

    const int bm = blockIdx.y, bn = blockIdx.x;
    const float* Ap = A + (size_t)(bm * 128) * NK_;
    const float* Bp = W + (size_t)(bn * 128) * NK_;

    const int lrow = tid >> 2;             // 0..63 (rows lrow, lrow+64)
    const int lcol = (tid & 3) * 4;

    float c[2][8][4];
#pragma unroll
    for (int i = 0; i < 2; i++)
#pragma unroll
        for (int j = 0; j < 8; j++)
#pragma unroll
            for (int e = 0; e < 4; e++) c[i][j][e] = 0.f;

    float4 ar[2], br[2];
#pragma unroll
    for (int u = 0; u < 2; u++) {
        ar[u] = *(const float4*)(Ap + (size_t)(lrow + u * 64) * NK_ + lcol);
        br[u] = *(const float4*)(Bp + (size_t)(lrow + u * 64) * NK_ + lcol);
    }
    // STS buffer 0
    {
        float* da0 = Asm + lrow * PADG + lcol;
        float* db0 = Bsm + lrow * PADG + lcol;
#pragma unroll
        for (int u = 0; u < 2; u++) {
            float* da = da0 + u * 64 * PADG;
            da[0] = to_tf32(ar[u].x); da[1] = to_tf32(ar[u].y);
            da[2] = to_tf32(ar[u].z); da[3] = to_tf32(ar[u].w);
            float* db = db0 + u * 64 * PADG;
            db[0] = to_tf32(br[u].x); db[1] = to_tf32(br[u].y);
            db[2] = to_tf32(br[u].z); db[3] = to_tf32(br[u].w);
        }
    }
    __syncthreads();

    const int NT = NK_ / BK;   // 64
    for (int kb = 0; kb < NT; kb++) {
        const int cur = kb & 1;
        if (kb + 1 < NT) {
#pragma unroll
            for (int u = 0; u < 2; u++) {
                ar[u] = *(const float4*)(Ap + (size_t)(lrow + u * 64) * NK_ + (kb + 1) * BK + lcol);
                br[u] = *(const float4*)(Bp + (size_t)(lrow + u * 64) * NK_ + (kb + 1) * BK + lcol);
            }
        }
        const float* Ab = Asm + cur * 128 * PADG;
        const float* Bb = Bsm + cur * 128 * PADG;
#pragma unroll
        for (int ks = 0; ks < 2; ks++) {
            const int kk = ks * 8;
            uint32_t a[2][4], b[8][2];
#pragma unroll
            for (int i = 0; i < 2; i++) {
                const int mm = wm + i * 16;
                a[i][0] = __float_as_uint(Ab[(mm + r)     * PADG + kk + cq]);
                a[i][1] = __float_as_uint(Ab[(mm + r + 8) * PADG + kk + cq]);
                a[i][2] = __float_as_uint(Ab[(mm + r)     * PADG + kk + cq + 4]);
                a[i][3] = __float_as_uint(Ab[(mm + r + 8) * PADG + kk + cq + 4]);
            }
#pragma unroll
            for (int j = 0; j < 8; j++) {
                const int nn = wn + j * 8 + r;
                b[j][0] = __float_as_uint(Bb[nn * PADG + kk + cq]);
                b[j][1] = __float_as_uint(Bb[nn * PADG + kk + cq + 4]);
            }
#pragma unroll
            for (int i = 0; i < 2; i++)
#pragma unroll
                for (int j = 0; j < 8; j++)
                    mma_tf32(c[i][j], a[i], b[j]);
        }
        if (kb + 1 < NT) {
            const int nxt = (kb + 1) & 1;
            float* da0 = Asm + nxt * 128 * PADG + lrow * PADG + lcol;
            float* db0 = Bsm + nxt * 128 * PADG + lrow * PADG + lcol;
#pragma unroll
            for (int u = 0; u < 2; u++) {
                float* da = da0 + u * 64 * PADG;
                da[0] = to_tf32(ar[u].x); da[1] = to_tf32(ar[u].y);
                da[2] = to_tf32(ar[u].z); da[3] = to_tf32(ar[u].w);
                float* db = db0 + u * 64 * PADG;
                db[0] = to_tf32(br[u].x); db[1] = to_tf32(br[u].y);
                db[2] = to_tf32(br[u].z); db[3] = to_tf32(br[u].w);
            }
        }
        __syncthreads();
    }

    // Epilogue
#pragma unroll
    for (int i = 0; i < 2; i++) {
#pragma unroll
        for (int j = 0; j < 8; j++) {
            const int row = bm * 128 + wm + 16 * i + r;
            const int col = bn * 128 + wn + 8 * j + 2 * cq;
            float v0 = c[i][j][0], v1 = c[i][j][1];
            float v2 = c[i][j][2], v3 = c[i][j][3];
            if (mode == 1) {
                const int h = col >> 6, d = col & 63;
                const int bb = row >> 11, t = row & 2047;
                float* dst = OUT + (((size_t)bb * H_ + h) * T_ + t) * D_ + d;
                float2 p0 = { v0, v1 };
                *(float2*)dst = p0;
                float* dst2 = OUT + (((size_t)bb * H_ + h) * T_ + (t + 8)) * D_ + d;
                float2 p1 = { v2, v3 };
                *(float2*)dst2 = p1;
            } else {
                float b0 = 0.f, b1 = 0.f;
                if (mode == 2) { b0 = bias[col]; b1 = bias[col + 1]; }
                float* dst = OUT + (size_t)row * NK_ + col;
                float2 p0 = { v0 + b0, v1 + b1 };
                *(float2*)dst = p0;
                float* dst2 = OUT + (size_t)(row + 8) * NK_ + col;
                float2 p1 = { v2 + b0, v3 + b1 };
                *(float2*)dst2 = p1;
            }
        }
    }
}

// ---------------------------------------------------------------------------
// TF32 flash attention. Block = 64 queries of one (b,h), 4 warps.
// Warp owns 16 query rows x all 64 key cols. Online softmax in registers.
// ---------------------------------------------------------------------------
#define SQ 68
#define SV 72
#define ATT_SMEM ((3 * 64 * SQ + 64 * SV) * 4)   // 70656 B

__global__ __launch_bounds__(128)
void attn_tf32(void)
{
    extern __shared__ float sm[];
    float* Qs = sm;
    float* Ks = Qs + 64 * SQ;
    float* Ps = Ks + 64 * SQ;
    float* Vs = Ps + 64 * SQ;

    const int tid = threadIdx.x, lane = tid & 31, wid = tid >> 5;
    const int qt = blockIdx.x, bh = blockIdx.y;
    const int m0 = wid * 16;
    const int r = lane >> 2, cq = lane & 3;

    const float* Qb = g_Q + ((size_t)bh * T_ + qt * 64) * D_;
#pragma unroll
    for (int u = 0; u < 8; u++) {
        int f = tid + u * 128;
        int row = f >> 4, col = (f & 15) * 4;
        float4 v = *(const float4*)(Qb + row * D_ + col);
        float* d = Qs + row * SQ + col;
        d[0] = to_tf32(v.x); d[1] = to_tf32(v.y);
        d[2] = to_tf32(v.z); d[3] = to_tf32(v.w);
    }

    float o[8][4];
#pragma unroll
    for (int j = 0; j < 8; j++)
#pragma unroll
        for (int e = 0; e < 4; e++) o[j][e] = 0.f;
    float mr0 = -1e30f, mr1 = -1e30f, l0 = 0.f, l1 = 0.f;

    for (int kt = 0; kt <= qt; kt++) {
        __syncthreads();
        const float* Kb = g_K + ((size_t)bh * T_ + kt * 64) * D_;
        const float* Vb = g_V + ((size_t)bh * T_ + kt * 64) * D_;
#pragma unroll
        for (int u = 0; u < 8; u++) {
            int f = tid + u * 128;
            int row = f >> 4, col = (f & 15) * 4;
            float4 v = *(const float4*)(Kb + row * D_ + col);
            float* d = Ks + row * SQ + col;
            d[0] = to_tf32(v.x); d[1] = to_tf32(v.y);
            d[2] = to_tf32(v.z); d[3] = to_tf32(v.w);
            float4 w = *(const float4*)(Vb + row * D_ + col);
            float* e = Vs + row * SV + col;
            e[0] = to_tf32(w.x); e[1] = to_tf32(w.y);
            e[2] = to_tf32(w.z); e[3] = to_tf32(w.w);
        }
        __syncthreads();

        // S = Q K^T
        float s[8][4];
#pragma unroll
        for (int j = 0; j < 8; j++)
#pragma unroll
            for (int e = 0; e < 4; e++) s[j][e] = 0.f;
#pragma unroll
        for (int ks = 0; ks < 8; ks++) {
            const int kk = ks * 8;
            uint32_t a[4];
            a[0] = __float_as_uint(Qs[(m0 + r)     * SQ + kk + cq]);
            a[1] = __float_as_uint(Qs[(m0 + r + 8) * SQ + kk + cq]);
            a[2] = __float_as_uint(Qs[(m0 + r)     * SQ + kk + cq + 4]);
            a[3] = __float_as_uint(Qs[(m0 + r + 8) * SQ + kk + cq + 4]);
#pragma unroll
            for (int j = 0; j < 8; j++) {
                uint32_t b[2];
                b[0] = __float_as_uint(Ks[(j * 8 + r) * SQ + kk + cq]);
                b[1] = __float_as_uint(Ks[(j * 8 + r) * SQ + kk + cq + 4]);
                mma_tf32(s[j], a, b);
            }
        }

        const float sc = 0.125f;
        if (kt == qt) {
            const int r0l = m0 + r, r1l = r0l + 8;
#pragma unroll
            for (int j = 0; j < 8; j++) {
                const int col = j * 8 + 2 * cq;
                s[j][0] = (col     <= r0l) ? s[j][0] * sc : -1e30f;
                s[j][1] = (col + 1 <= r0l) ? s[j][1] * sc : -1e30f;
                s[j][2] = (col     <= r1l) ? s[j][2] * sc : -1e30f;
                s[j][3] = (col + 1 <= r1l) ? s[j][3] * sc : -1e30f;
            }
        } else {
#pragma unroll
            for (int j = 0; j < 8; j++)
#pragma unroll
                for (int e = 0; e < 4; e++) s[j][e] *= sc;
        }

        // row maxes (rows r and r+8 of this warp's 16)
        float mx0 = -1e30f, mx1 = -1e30f;
#pragma unroll
        for (int j = 0; j < 8; j++) {
            mx0 = fmaxf(mx0, fmaxf(s[j][0], s[j][1]));
            mx1 = fmaxf(mx1, fmaxf(s[j][2], s[j][3]));
        }
        mx0 = fmaxf(mx0, __shfl_xor_sync(0xffffffffu, mx0, 1));
        mx0 = fmaxf(mx0, __shfl_xor_sync(0xffffffffu, mx0, 2));
        mx1 = fmaxf(mx1, __shfl_xor_sync(0xffffffffu, mx1, 1));
        mx1 = fmaxf(mx1, __shfl_xor_sync(0xffffffffu, mx1, 2));

        const float nm0 = fmaxf(mr0, mx0), nm1 = fmaxf(mr1, mx1);
        const float al0 = __expf(mr0 - nm0), al1 = __expf(mr1 - nm1);
        mr0 = nm0; mr1 = nm1;

        float ls0 = 0.f, ls1 = 0.f;
#pragma unroll
        for (int j = 0; j < 8; j++) {
            float p0 = to_tf32(__expf(s[j][0] - nm0));
            float p1 = to_tf32(__expf(s[j][1] - nm0));
            float p2 = to_tf32(__expf(s[j][2] - nm1));
            float p3 = to_tf32(__expf(s[j][3] - nm1));
            ls0 += p0 + p1; ls1 += p2 + p3;
            float2 w0 = { p0, p1 };
            *(float2*)(Ps + (m0 + r)     * SQ + j * 8 + 2 * cq) = w0;
            float2 w1 = { p2, p3 };
            *(float2*)(Ps + (m0 + r + 8) * SQ + j * 8 + 2 * cq) = w1;
        }
        ls0 += __shfl_xor_sync(0xffffffffu, ls0, 1);
        ls0 += __shfl_xor_sync(0xffffffffu, ls0, 2);
        ls1 += __shfl_xor_sync(0xffffffffu, ls1, 1);
        ls1 += __shfl_xor_sync(0xffffffffu, ls1, 2);
        l0 = l0 * al0 + ls0;
        l1 = l1 * al1 + ls1;

#pragma unroll
        for (int j = 0; j < 8; j++) {
            o[j][0] *= al0; o[j][1] *= al0;
            o[j][2] *= al1; o[j][3] *= al1;
        }
        __syncwarp();   // Ps is warp-local: rows m0..m0+15 written/read by this warp only

        // O += P V
#pragma unroll
        for (int ks = 0; ks < 8; ks++) {
            const int kk = ks * 8;
            uint32_t a[4];
            a[0] = __float_as_uint(Ps[(m0 + r)     * SQ + kk + cq]);
            a[1] = __float_as_uint(Ps[(m0 + r + 8) * SQ + kk + cq]);
            a[2] = __float_as_uint(Ps[(m0 + r)     * SQ + kk + cq + 4]);
            a[3] = __float_as_uint(Ps[(m0 + r + 8) * SQ + kk + cq + 4]);
#pragma unroll
            for (int j = 0; j < 8; j++) {
                uint32_t b[2];
                b[0] = __float_as_uint(Vs[(kk + cq)     * SV + j * 8 + r]);
                b[1] = __float_as_uint(Vs[(kk + cq + 4) * SV + j * 8 + r]);
                mma_tf32(o[j], a, b);
            }
        }
    }

    // Epilogue: normalize, write [B,T,C]
    const int b = bh >> 4, h = bh & 15;
    const float inv0 = 1.f / l0, inv1 = 1.f / l1;
    const int t0 = qt * 64 + m0 + r;
#pragma unroll
    for (int j = 0; j < 8; j++) {
        const int d = j * 8 + 2 * cq;
        float2 w0 = { o[j][0] * inv0, o[j][1] * inv0 };
        *(float2*)(g_Y + ((size_t)b * T_ + t0)     * C_ + h * 64 + d) = w0;
        float2 w1 = { o[j][2] * inv1, o[j][3] * inv1 };
        *(float2*)(g_Y + ((size_t)b * T_ + t0 + 8) * C_ + h * 64 + d) = w1;
    }
}

// ---------------------------------------------------------------------------
extern "C" void kernel_launch(void* const* d_in, const int* in_sizes, int n_in,
                              void* d_out, int out_size)
{
    const float* X  = (const float*)d_in[0];
    const float* Wq = (const float*)d_in[1];
    const float* Wk = (const float*)d_in[2];
    const float* Wv = (const float*)d_in[3];
    const float* Wo = (const float*)d_in[4];
    const float* bo = (const float*)d_in[5];
    float* out = (float*)d_out;

    dim3 ggrid(NK_ / 128, M_ / 128);   // (8, 64)

    gemm_tf32<<<ggrid, 256, GEMM_SMEM>>>(X, -1, Wq, nullptr, 0, nullptr, 1);
    gemm_tf32<<<ggrid, 256, GEMM_SMEM>>>(X, -1, Wk, nullptr, 1, nullptr, 1);
    gemm_tf32<<<ggrid, 256, GEMM_SMEM>>>(X, -1, Wv, nullptr, 2, nullptr, 1);

    cudaFuncSetAttribute(attn_tf32,
                         cudaFuncAttributeMaxDynamicSharedMemorySize, ATT_SMEM);
    attn_tf32<<<dim3(T_ / 64, B_ * H_), 128, ATT_SMEM>>>();

    gemm_tf32<<<ggrid, 256, GEMM_SMEM>>>(nullptr, 3, Wo, out, -1, bo, 2);
}

// round 7
// speedup vs baseline: 4.8524x; 1.3040x over previous
#include <cuda_runtime.h>
#include <cuda_fp16.h>
#include <cstdint>

#define B_  4
#define T_  2048
#define C_  1024
#define H_  16
#define D_  64
#define M_  (B_ * T_)
#define NK_ 1024

__device__ float g_Q[(size_t)B_ * H_ * T_ * D_];
__device__ float g_K[(size_t)B_ * H_ * T_ * D_];
__device__ float g_V[(size_t)B_ * H_ * T_ * D_];
__device__ float g_Y[(size_t)M_ * C_];

__device__ __forceinline__ void mma_fp16(float c[4], const uint32_t a[4], const uint32_t b[2]) {
    asm volatile(
        "mma.sync.aligned.m16n8k16.row.col.f32.f16.f16.f32 "
        "{%0,%1,%2,%3}, {%4,%5,%6,%7}, {%8,%9}, {%0,%1,%2,%3};"
        : "+f"(c[0]), "+f"(c[1]), "+f"(c[2]), "+f"(c[3])
        : "r"(a[0]), "r"(a[1]), "r"(a[2]), "r"(a[3]), "r"(b[0]), "r"(b[1]));
}

// ---------------------------------------------------------------------------
// FP16 GEMM-NT: out[m][n] = sum_k A[m][k]*W[n][k] (+bias)
// Block 128x128, warp 32x64, BK=16 (one k16 MMA step per stage),
// double-buffered smem with register prefetch. fp32->half at STS.
// ---------------------------------------------------------------------------
#define PADH 24   // halfs per row (16 + 8 pad) = 48 B

__global__ __launch_bounds__(256, 2)
void gemm_fp16(const float* __restrict__ A_ext, int a_sel,
               const float* __restrict__ W,
               float* __restrict__ out_ext, int out_sel,
               const float* __restrict__ bias, int mode)
{
    __shared__ __half As[2][128 * PADH];
    __shared__ __half Bs[2][128 * PADH];

    const float* A = (a_sel < 0) ? A_ext : g_Y;
    float* OUT = (out_sel < 0) ? out_ext
               : (out_sel == 0 ? g_Q : (out_sel == 1 ? g_K : g_V));

    const int tid  = threadIdx.x;
    const int lane = tid & 31, wid = tid >> 5;
    const int wm = (wid >> 1) * 32;
    const int wn = (wid & 1) * 64;
    const int r = lane >> 2, cq = lane & 3;

    const int bm = blockIdx.y, bn = blockIdx.x;
    const float* Ap = A + (size_t)(bm * 128) * NK_;
    const float* Bp = W + (size_t)(bn * 128) * NK_;

    const int lrow = tid >> 2;           // 0..63 (rows lrow, lrow+64)
    const int lcol = (tid & 3) * 4;      // 0,4,8,12

    float c[2][8][4];
#pragma unroll
    for (int i = 0; i < 2; i++)
#pragma unroll
        for (int j = 0; j < 8; j++)
#pragma unroll
            for (int e = 0; e < 4; e++) c[i][j][e] = 0.f;

    float4 ar[2], br[2];
#pragma unroll
    for (int u = 0; u < 2; u++) {
        ar[u] = *(const float4*)(Ap + (size_t)(lrow + u * 64) * NK_ + lcol);
        br[u] = *(const float4*)(Bp + (size_t)(lrow + u * 64) * NK_ + lcol);
    }
    {
#pragma unroll
        for (int u = 0; u < 2; u++) {
            const int row = lrow + u * 64;
            __half2 a01 = __floats2half2_rn(ar[u].x, ar[u].y);
            __half2 a23 = __floats2half2_rn(ar[u].z, ar[u].w);
            uint2 pa = { *(uint32_t*)&a01, *(uint32_t*)&a23 };
            *(uint2*)&As[0][row * PADH + lcol] = pa;
            __half2 b01 = __floats2half2_rn(br[u].x, br[u].y);
            __half2 b23 = __floats2half2_rn(br[u].z, br[u].w);
            uint2 pb = { *(uint32_t*)&b01, *(uint32_t*)&b23 };
            *(uint2*)&Bs[0][row * PADH + lcol] = pb;
        }
    }
    __syncthreads();

    const int NT = NK_ / 16;   // 64 stages
    for (int kb = 0; kb < NT; kb++) {
        const int cur = kb & 1;
        if (kb + 1 < NT) {
#pragma unroll
            for (int u = 0; u < 2; u++) {
                ar[u] = *(const float4*)(Ap + (size_t)(lrow + u * 64) * NK_ + (kb + 1) * 16 + lcol);
                br[u] = *(const float4*)(Bp + (size_t)(lrow + u * 64) * NK_ + (kb + 1) * 16 + lcol);
            }
        }
        const __half* Ab = As[cur];
        const __half* Bb = Bs[cur];

        uint32_t a[2][4], b[8][2];
#pragma unroll
        for (int i = 0; i < 2; i++) {
            const int mm = wm + 16 * i;
            a[i][0] = *(const uint32_t*)&Ab[(mm + r)     * PADH + 2 * cq];
            a[i][1] = *(const uint32_t*)&Ab[(mm + r + 8) * PADH + 2 * cq];
            a[i][2] = *(const uint32_t*)&Ab[(mm + r)     * PADH + 2 * cq + 8];
            a[i][3] = *(const uint32_t*)&Ab[(mm + r + 8) * PADH + 2 * cq + 8];
        }
#pragma unroll
        for (int j = 0; j < 8; j++) {
            const int nn = wn + j * 8 + r;
            b[j][0] = *(const uint32_t*)&Bb[nn * PADH + 2 * cq];
            b[j][1] = *(const uint32_t*)&Bb[nn * PADH + 2 * cq + 8];
        }
#pragma unroll
        for (int i = 0; i < 2; i++)
#pragma unroll
            for (int j = 0; j < 8; j++)
                mma_fp16(c[i][j], a[i], b[j]);

        if (kb + 1 < NT) {
            const int nxt = (kb + 1) & 1;
#pragma unroll
            for (int u = 0; u < 2; u++) {
                const int row = lrow + u * 64;
                __half2 a01 = __floats2half2_rn(ar[u].x, ar[u].y);
                __half2 a23 = __floats2half2_rn(ar[u].z, ar[u].w);
                uint2 pa = { *(uint32_t*)&a01, *(uint32_t*)&a23 };
                *(uint2*)&As[nxt][row * PADH + lcol] = pa;
                __half2 b01 = __floats2half2_rn(br[u].x, br[u].y);
                __half2 b23 = __floats2half2_rn(br[u].z, br[u].w);
                uint2 pb = { *(uint32_t*)&b01, *(uint32_t*)&b23 };
                *(uint2*)&Bs[nxt][row * PADH + lcol] = pb;
            }
        }
        __syncthreads();
    }

    // Epilogue (c-frag layout identical to tf32 m16n8k8)
#pragma unroll
    for (int i = 0; i < 2; i++) {
#pragma unroll
        for (int j = 0; j < 8; j++) {
            const int row = bm * 128 + wm + 16 * i + r;
            const int col = bn * 128 + wn + 8 * j + 2 * cq;
            float v0 = c[i][j][0], v1 = c[i][j][1];
            float v2 = c[i][j][2], v3 = c[i][j][3];
            if (mode == 1) {
                const int h = col >> 6, d = col & 63;
                const int bb = row >> 11, t = row & 2047;
                float2 p0 = { v0, v1 };
                *(float2*)(OUT + (((size_t)bb * H_ + h) * T_ + t) * D_ + d) = p0;
                float2 p1 = { v2, v3 };
                *(float2*)(OUT + (((size_t)bb * H_ + h) * T_ + (t + 8)) * D_ + d) = p1;
            } else {
                float b0 = 0.f, b1 = 0.f;
                if (mode == 2) { b0 = bias[col]; b1 = bias[col + 1]; }
                float2 p0 = { v0 + b0, v1 + b1 };
                *(float2*)(OUT + (size_t)row * NK_ + col) = p0;
                float2 p1 = { v2 + b0, v3 + b1 };
                *(float2*)(OUT + (size_t)(row + 8) * NK_ + col) = p1;
            }
        }
    }
}

// ---------------------------------------------------------------------------
// FP16 flash attention. Block = 64 queries of one (b,h), 4 warps.
// Warp owns 16 query rows x 64 key cols. fp32 softmax stats in registers.
// V stored transposed (Vt[d][s]) for the PV mma B-fragments.
// ---------------------------------------------------------------------------
#define SQH 72   // halfs per row for Qh/Kh/Ph
#define SVT 66   // halfs per row for Vt

__global__ __launch_bounds__(128)
void attn_fp16(void)
{
    __shared__ __half Qh[64 * SQH];
    __shared__ __half Kh[64 * SQH];
    __shared__ __half Ph[64 * SQH];
    __shared__ __half Vt[64 * SVT];

    const int tid = threadIdx.x, lane = tid & 31, wid = tid >> 5;
    const int qt = blockIdx.x, bh = blockIdx.y;
    const int m0 = wid * 16;
    const int r = lane >> 2, cq = lane & 3;

    const float* Qb = g_Q + ((size_t)bh * T_ + qt * 64) * D_;
#pragma unroll
    for (int u = 0; u < 8; u++) {
        int f = tid + u * 128;
        int row = f >> 4, col = (f & 15) * 4;
        float4 v = *(const float4*)(Qb + row * D_ + col);
        __half2 h01 = __floats2half2_rn(v.x, v.y);
        __half2 h23 = __floats2half2_rn(v.z, v.w);
        uint2 p = { *(uint32_t*)&h01, *(uint32_t*)&h23 };
        *(uint2*)&Qh[row * SQH + col] = p;
    }

    float o[8][4];
#pragma unroll
    for (int j = 0; j < 8; j++)
#pragma unroll
        for (int e = 0; e < 4; e++) o[j][e] = 0.f;
    float mr0 = -1e30f, mr1 = -1e30f, l0 = 0.f, l1 = 0.f;

    for (int kt = 0; kt <= qt; kt++) {
        __syncthreads();
        const float* Kb = g_K + ((size_t)bh * T_ + kt * 64) * D_;
        const float* Vb = g_V + ((size_t)bh * T_ + kt * 64) * D_;
#pragma unroll
        for (int u = 0; u < 8; u++) {
            int f = tid + u * 128;
            int row = f >> 4, col = (f & 15) * 4;
            float4 v = *(const float4*)(Kb + row * D_ + col);
            __half2 h01 = __floats2half2_rn(v.x, v.y);
            __half2 h23 = __floats2half2_rn(v.z, v.w);
            uint2 p = { *(uint32_t*)&h01, *(uint32_t*)&h23 };
            *(uint2*)&Kh[row * SQH + col] = p;
            // V transposed: Vt[d][s]
            float4 w = *(const float4*)(Vb + row * D_ + col);
            Vt[(col + 0) * SVT + row] = __float2half_rn(w.x);
            Vt[(col + 1) * SVT + row] = __float2half_rn(w.y);
            Vt[(col + 2) * SVT + row] = __float2half_rn(w.z);
            Vt[(col + 3) * SVT + row] = __float2half_rn(w.w);
        }
        __syncthreads();

        // S = Q K^T  (4 k16 steps)
        float s[8][4];
#pragma unroll
        for (int j = 0; j < 8; j++)
#pragma unroll
            for (int e = 0; e < 4; e++) s[j][e] = 0.f;
#pragma unroll
        for (int ks = 0; ks < 4; ks++) {
            const int kk = ks * 16;
            uint32_t a[4];
            a[0] = *(const uint32_t*)&Qh[(m0 + r)     * SQH + kk + 2 * cq];
            a[1] = *(const uint32_t*)&Qh[(m0 + r + 8) * SQH + kk + 2 * cq];
            a[2] = *(const uint32_t*)&Qh[(m0 + r)     * SQH + kk + 2 * cq + 8];
            a[3] = *(const uint32_t*)&Qh[(m0 + r + 8) * SQH + kk + 2 * cq + 8];
#pragma unroll
            for (int j = 0; j < 8; j++) {
                uint32_t b[2];
                b[0] = *(const uint32_t*)&Kh[(j * 8 + r) * SQH + kk + 2 * cq];
                b[1] = *(const uint32_t*)&Kh[(j * 8 + r) * SQH + kk + 2 * cq + 8];
                mma_fp16(s[j], a, b);
            }
        }

        const float sc = 0.125f;
        if (kt == qt) {
            const int r0l = m0 + r, r1l = r0l + 8;
#pragma unroll
            for (int j = 0; j < 8; j++) {
                const int col = j * 8 + 2 * cq;
                s[j][0] = (col     <= r0l) ? s[j][0] * sc : -1e30f;
                s[j][1] = (col + 1 <= r0l) ? s[j][1] * sc : -1e30f;
                s[j][2] = (col     <= r1l) ? s[j][2] * sc : -1e30f;
                s[j][3] = (col + 1 <= r1l) ? s[j][3] * sc : -1e30f;
            }
        } else {
#pragma unroll
            for (int j = 0; j < 8; j++)
#pragma unroll
                for (int e = 0; e < 4; e++) s[j][e] *= sc;
        }

        float mx0 = -1e30f, mx1 = -1e30f;
#pragma unroll
        for (int j = 0; j < 8; j++) {
            mx0 = fmaxf(mx0, fmaxf(s[j][0], s[j][1]));
            mx1 = fmaxf(mx1, fmaxf(s[j][2], s[j][3]));
        }
        mx0 = fmaxf(mx0, __shfl_xor_sync(0xffffffffu, mx0, 1));
        mx0 = fmaxf(mx0, __shfl_xor_sync(0xffffffffu, mx0, 2));
        mx1 = fmaxf(mx1, __shfl_xor_sync(0xffffffffu, mx1, 1));
        mx1 = fmaxf(mx1, __shfl_xor_sync(0xffffffffu, mx1, 2));

        const float nm0 = fmaxf(mr0, mx0), nm1 = fmaxf(mr1, mx1);
        const float al0 = __expf(mr0 - nm0), al1 = __expf(mr1 - nm1);
        mr0 = nm0; mr1 = nm1;

        float ls0 = 0.f, ls1 = 0.f;
#pragma unroll
        for (int j = 0; j < 8; j++) {
            __half2 h01 = __floats2half2_rn(__expf(s[j][0] - nm0), __expf(s[j][1] - nm0));
            __half2 h23 = __floats2half2_rn(__expf(s[j][2] - nm1), __expf(s[j][3] - nm1));
            float2 f01 = __half22float2(h01);
            float2 f23 = __half22float2(h23);
            ls0 += f01.x + f01.y;
            ls1 += f23.x + f23.y;
            *(uint32_t*)&Ph[(m0 + r)     * SQH + j * 8 + 2 * cq] = *(uint32_t*)&h01;
            *(uint32_t*)&Ph[(m0 + r + 8) * SQH + j * 8 + 2 * cq] = *(uint32_t*)&h23;
        }
        ls0 += __shfl_xor_sync(0xffffffffu, ls0, 1);
        ls0 += __shfl_xor_sync(0xffffffffu, ls0, 2);
        ls1 += __shfl_xor_sync(0xffffffffu, ls1, 1);
        ls1 += __shfl_xor_sync(0xffffffffu, ls1, 2);
        l0 = l0 * al0 + ls0;
        l1 = l1 * al1 + ls1;

#pragma unroll
        for (int j = 0; j < 8; j++) {
            o[j][0] *= al0; o[j][1] *= al0;
            o[j][2] *= al1; o[j][3] *= al1;
        }
        __syncwarp();   // Ph rows m0..m0+15 are warp-local

        // O += P V  (4 k16 steps over s; B from Vt[d][s])
#pragma unroll
        for (int ks = 0; ks < 4; ks++) {
            const int kk = ks * 16;
            uint32_t a[4];
            a[0] = *(const uint32_t*)&Ph[(m0 + r)     * SQH + kk + 2 * cq];
            a[1] = *(const uint32_t*)&Ph[(m0 + r + 8) * SQH + kk + 2 * cq];
            a[2] = *(const uint32_t*)&Ph[(m0 + r)     * SQH + kk + 2 * cq + 8];
            a[3] = *(const uint32_t*)&Ph[(m0 + r + 8) * SQH + kk + 2 * cq + 8];
#pragma unroll
            for (int j = 0; j < 8; j++) {
                uint32_t b[2];
                b[0] = *(const uint32_t*)&Vt[(j * 8 + r) * SVT + kk + 2 * cq];
                b[1] = *(const uint32_t*)&Vt[(j * 8 + r) * SVT + kk + 2 * cq + 8];
                mma_fp16(o[j], a, b);
            }
        }
    }

    // Epilogue: normalize, write [B,T,C] fp32
    const int b = bh >> 4, h = bh & 15;
    const float inv0 = 1.f / l0, inv1 = 1.f / l1;
    const int t0 = qt * 64 + m0 + r;
#pragma unroll
    for (int j = 0; j < 8; j++) {
        const int d = j * 8 + 2 * cq;
        float2 w0 = { o[j][0] * inv0, o[j][1] * inv0 };
        *(float2*)(g_Y + ((size_t)b * T_ + t0)     * C_ + h * 64 + d) = w0;
        float2 w1 = { o[j][2] * inv1, o[j][3] * inv1 };
        *(float2*)(g_Y + ((size_t)b * T_ + t0 + 8) * C_ + h * 64 + d) = w1;
    }
}

// ---------------------------------------------------------------------------
extern "C" void kernel_launch(void* const* d_in, const int* in_sizes, int n_in,
                              void* d_out, int out_size)
{
    const float* X  = (const float*)d_in[0];
    const float* Wq = (const float*)d_in[1];
    const float* Wk = (const float*)d_in[2];
    const float* Wv = (const float*)d_in[3];
    const float* Wo = (const float*)d_in[4];
    const float* bo = (const float*)d_in[5];
    float* out = (float*)d_out;

    dim3 ggrid(NK_ / 128, M_ / 128);   // (8, 64)

    gemm_fp16<<<ggrid, 256>>>(X, -1, Wq, nullptr, 0, nullptr, 1);
    gemm_fp16<<<ggrid, 256>>>(X, -1, Wk, nullptr, 1, nullptr, 1);
    gemm_fp16<<<ggrid, 256>>>(X, -1, Wv, nullptr, 2, nullptr, 1);

    attn_fp16<<<dim3(T_ / 64, B_ * H_), 128>>>();

    gemm_fp16<<<ggrid, 256>>>(nullptr, 3, Wo, out, -1, bo, 2);
}

// round 8
// speedup vs baseline: 5.8536x; 1.2063x over previous
#include <cuda_runtime.h>
#include <cuda_fp16.h>
#include <cstdint>

#define B_  4
#define T_  2048
#define C_  1024
#define H_  16
#define D_  64
#define M_  (B_ * T_)
#define NK_ 1024

__device__ float g_Q[(size_t)B_ * H_ * T_ * D_];
__device__ float g_K[(size_t)B_ * H_ * T_ * D_];
__device__ float g_V[(size_t)B_ * H_ * T_ * D_];
__device__ float g_Y[(size_t)M_ * C_];

__device__ __forceinline__ uint32_t smem_u32(const void* p) {
    uint32_t a;
    asm("{ .reg .u64 t; cvta.to.shared.u64 t, %1; cvt.u32.u64 %0, t; }"
        : "=r"(a) : "l"(p));
    return a;
}
__device__ __forceinline__ uint32_t f2h2(float x, float y) {
    __half2 h = __floats2half2_rn(x, y);
    return *(uint32_t*)&h;
}
__device__ __forceinline__ void mma_fp16(float c[4], const uint32_t a[4], const uint32_t b[2]) {
    asm volatile(
        "mma.sync.aligned.m16n8k16.row.col.f32.f16.f16.f32 "
        "{%0,%1,%2,%3}, {%4,%5,%6,%7}, {%8,%9}, {%0,%1,%2,%3};"
        : "+f"(c[0]), "+f"(c[1]), "+f"(c[2]), "+f"(c[3])
        : "r"(a[0]), "r"(a[1]), "r"(a[2]), "r"(a[3]), "r"(b[0]), "r"(b[1]));
}
#define LDSM4(r0, r1, r2, r3, a) \
    asm volatile("ldmatrix.sync.aligned.m8n8.x4.shared.b16 {%0,%1,%2,%3}, [%4];" \
        : "=r"(r0), "=r"(r1), "=r"(r2), "=r"(r3) : "r"(a))
#define LDSM4T(r0, r1, r2, r3, a) \
    asm volatile("ldmatrix.sync.aligned.m8n8.x4.trans.shared.b16 {%0,%1,%2,%3}, [%4];" \
        : "=r"(r0), "=r"(r1), "=r"(r2), "=r"(r3) : "r"(a))

// ---------------------------------------------------------------------------
// FP16 GEMM-NT: out[m][n] = sum_k A[m][k]*W[n][k] (+bias)
// Block 128x128, warp 32x64, BK=32, ldmatrix frags, double-buffered smem.
// ---------------------------------------------------------------------------
#define PADG 40   // halfs per row (32 + 8)

__global__ __launch_bounds__(256, 2)
void gemm_fp16(const float* __restrict__ A_ext, int a_sel,
               const float* __restrict__ W,
               float* __restrict__ out_ext, int out_sel,
               const float* __restrict__ bias, int mode)
{
    __shared__ __half As[2][128 * PADG];
    __shared__ __half Bs[2][128 * PADG];

    const float* A = (a_sel < 0) ? A_ext : g_Y;
    float* OUT = (out_sel < 0) ? out_ext
               : (out_sel == 0 ? g_Q : (out_sel == 1 ? g_K : g_V));

    const int tid  = threadIdx.x;
    const int lane = tid & 31, wid = tid >> 5;
    const int wm = (wid >> 1) * 32;
    const int wn = (wid & 1) * 64;
    const int r = lane >> 2, cq = lane & 3;

    const int bm = blockIdx.y, bn = blockIdx.x;
    const float* Ap = A + (size_t)(bm * 128) * NK_;
    const float* Bp = W + (size_t)(bn * 128) * NK_;

    const int lrow = tid >> 3;          // 0..31 (rows lrow + 32u)
    const int lcol = (tid & 7) * 4;     // 0..28

    const uint32_t sA = smem_u32(As), sB = smem_u32(Bs);
    const int eL = lane & 7;
    const uint32_t a_loff = ((wm + 8 * ((lane >> 3) & 1) + eL) * PADG + 8 * (lane >> 4)) * 2;
    const uint32_t b_loff = ((wn + 8 * (lane >> 4) + eL) * PADG + 8 * ((lane >> 3) & 1)) * 2;

    float c[2][8][4];
#pragma unroll
    for (int i = 0; i < 2; i++)
#pragma unroll
        for (int j = 0; j < 8; j++)
#pragma unroll
            for (int e = 0; e < 4; e++) c[i][j][e] = 0.f;

    uint2 pa[4], pb[4];
#pragma unroll
    for (int u = 0; u < 4; u++) {
        float4 va = *(const float4*)(Ap + (size_t)(lrow + u * 32) * NK_ + lcol);
        pa[u] = make_uint2(f2h2(va.x, va.y), f2h2(va.z, va.w));
        float4 vb = *(const float4*)(Bp + (size_t)(lrow + u * 32) * NK_ + lcol);
        pb[u] = make_uint2(f2h2(vb.x, vb.y), f2h2(vb.z, vb.w));
    }
#pragma unroll
    for (int u = 0; u < 4; u++) {
        *(uint2*)&As[0][(lrow + u * 32) * PADG + lcol] = pa[u];
        *(uint2*)&Bs[0][(lrow + u * 32) * PADG + lcol] = pb[u];
    }
    __syncthreads();

    const int NT = NK_ / 32;   // 32 stages
    for (int kb = 0; kb < NT; kb++) {
        const int cur = kb & 1;
        if (kb + 1 < NT) {
#pragma unroll
            for (int u = 0; u < 4; u++) {
                float4 va = *(const float4*)(Ap + (size_t)(lrow + u * 32) * NK_ + (kb + 1) * 32 + lcol);
                pa[u] = make_uint2(f2h2(va.x, va.y), f2h2(va.z, va.w));
                float4 vb = *(const float4*)(Bp + (size_t)(lrow + u * 32) * NK_ + (kb + 1) * 32 + lcol);
                pb[u] = make_uint2(f2h2(vb.x, vb.y), f2h2(vb.z, vb.w));
            }
        }
        const uint32_t abuf = sA + cur * 128 * PADG * 2;
        const uint32_t bbuf = sB + cur * 128 * PADG * 2;
#pragma unroll
        for (int t = 0; t < 2; t++) {
            uint32_t a[2][4], b[8][2];
#pragma unroll
            for (int i = 0; i < 2; i++)
                LDSM4(a[i][0], a[i][1], a[i][2], a[i][3],
                      abuf + a_loff + (i * 16 * PADG + t * 16) * 2);
#pragma unroll
            for (int q = 0; q < 4; q++)
                LDSM4(b[2*q][0], b[2*q][1], b[2*q+1][0], b[2*q+1][1],
                      bbuf + b_loff + (q * 16 * PADG + t * 16) * 2);
#pragma unroll
            for (int i = 0; i < 2; i++)
#pragma unroll
                for (int j = 0; j < 8; j++)
                    mma_fp16(c[i][j], a[i], b[j]);
        }
        if (kb + 1 < NT) {
            const int nxt = (kb + 1) & 1;
#pragma unroll
            for (int u = 0; u < 4; u++) {
                *(uint2*)&As[nxt][(lrow + u * 32) * PADG + lcol] = pa[u];
                *(uint2*)&Bs[nxt][(lrow + u * 32) * PADG + lcol] = pb[u];
            }
        }
        __syncthreads();
    }

    // Epilogue
#pragma unroll
    for (int i = 0; i < 2; i++) {
#pragma unroll
        for (int j = 0; j < 8; j++) {
            const int row = bm * 128 + wm + 16 * i + r;
            const int col = bn * 128 + wn + 8 * j + 2 * cq;
            float v0 = c[i][j][0], v1 = c[i][j][1];
            float v2 = c[i][j][2], v3 = c[i][j][3];
            if (mode == 1) {
                const int h = col >> 6, d = col & 63;
                const int bb = row >> 11, t = row & 2047;
                float2 p0 = { v0, v1 };
                *(float2*)(OUT + (((size_t)bb * H_ + h) * T_ + t) * D_ + d) = p0;
                float2 p1 = { v2, v3 };
                *(float2*)(OUT + (((size_t)bb * H_ + h) * T_ + (t + 8)) * D_ + d) = p1;
            } else {
                float b0 = 0.f, b1 = 0.f;
                if (mode == 2) { b0 = bias[col]; b1 = bias[col + 1]; }
                float2 p0 = { v0 + b0, v1 + b1 };
                *(float2*)(OUT + (size_t)row * NK_ + col) = p0;
                float2 p1 = { v2 + b0, v3 + b1 };
                *(float2*)(OUT + (size_t)(row + 8) * NK_ + col) = p1;
            }
        }
    }
}

// ---------------------------------------------------------------------------
// FP16 flash attention (FA2-style). Block = 64 queries, 4 warps x 16 rows.
// Q frags in registers (loaded once), P kept in registers, K via ldmatrix,
// V row-major via ldmatrix.trans. fp32 softmax stats.
// ---------------------------------------------------------------------------
#define SKH 72   // halfs per row for Kh/Vh (64 + 8)

__global__ __launch_bounds__(128)
void attn_fp16(void)
{
    __shared__ __half Kh[64 * SKH];
    __shared__ __half Vh[64 * SKH];

    const int tid = threadIdx.x, lane = tid & 31, wid = tid >> 5;
    const int qt = (gridDim.x - 1) - blockIdx.x;   // longest blocks first
    const int bh = blockIdx.y;
    const int m0 = wid * 16;
    const int r = lane >> 2, cq = lane & 3;

    // ldmatrix per-lane offsets (bytes)
    const int eL = lane & 7;
    const uint32_t sK = smem_u32(Kh), sV = smem_u32(Vh);
    const uint32_t k_loff = ((8 * (lane >> 4) + eL) * SKH + 8 * ((lane >> 3) & 1)) * 2;
    const uint32_t v_loff = ((8 * ((lane >> 3) & 1) + eL) * SKH + 8 * (lane >> 4)) * 2;

    // Q fragments: registers, loaded once straight from global
    const float* Qb = g_Q + ((size_t)bh * T_ + qt * 64) * D_;
    uint32_t qa[4][4];
#pragma unroll
    for (int t = 0; t < 4; t++) {
        float2 v0 = *(const float2*)(Qb + (m0 + r)     * D_ + 16 * t + 2 * cq);
        float2 v1 = *(const float2*)(Qb + (m0 + r + 8) * D_ + 16 * t + 2 * cq);
        float2 v2 = *(const float2*)(Qb + (m0 + r)     * D_ + 16 * t + 8 + 2 * cq);
        float2 v3 = *(const float2*)(Qb + (m0 + r + 8) * D_ + 16 * t + 8 + 2 * cq);
        qa[t][0] = f2h2(v0.x, v0.y);
        qa[t][1] = f2h2(v1.x, v1.y);
        qa[t][2] = f2h2(v2.x, v2.y);
        qa[t][3] = f2h2(v3.x, v3.y);
    }

    float o[8][4];
#pragma unroll
    for (int j = 0; j < 8; j++)
#pragma unroll
        for (int e = 0; e < 4; e++) o[j][e] = 0.f;
    float mr0 = -1e30f, mr1 = -1e30f, l0 = 0.f, l1 = 0.f;

    for (int kt = 0; kt <= qt; kt++) {
        __syncthreads();
        const float* Kb = g_K + ((size_t)bh * T_ + kt * 64) * D_;
        const float* Vb = g_V + ((size_t)bh * T_ + kt * 64) * D_;
#pragma unroll
        for (int u = 0; u < 8; u++) {
            int f = tid + u * 128;
            int row = f >> 4, col = (f & 15) * 4;
            float4 v = *(const float4*)(Kb + row * D_ + col);
            *(uint2*)&Kh[row * SKH + col] = make_uint2(f2h2(v.x, v.y), f2h2(v.z, v.w));
            float4 w = *(const float4*)(Vb + row * D_ + col);
            *(uint2*)&Vh[row * SKH + col] = make_uint2(f2h2(w.x, w.y), f2h2(w.z, w.w));
        }
        __syncthreads();

        // S = Q K^T
        float s[8][4];
#pragma unroll
        for (int j = 0; j < 8; j++)
#pragma unroll
            for (int e = 0; e < 4; e++) s[j][e] = 0.f;
#pragma unroll
        for (int t = 0; t < 4; t++) {
            uint32_t b[8][2];
#pragma unroll
            for (int q = 0; q < 4; q++)
                LDSM4(b[2*q][0], b[2*q][1], b[2*q+1][0], b[2*q+1][1],
                      sK + k_loff + (q * 16 * SKH + t * 16) * 2);
#pragma unroll
            for (int j = 0; j < 8; j++)
                mma_fp16(s[j], qa[t], b[j]);
        }

        const float sc = 0.125f;
        if (kt == qt) {
            const int r0l = m0 + r, r1l = r0l + 8;
#pragma unroll
            for (int j = 0; j < 8; j++) {
                const int col = j * 8 + 2 * cq;
                s[j][0] = (col     <= r0l) ? s[j][0] * sc : -1e30f;
                s[j][1] = (col + 1 <= r0l) ? s[j][1] * sc : -1e30f;
                s[j][2] = (col     <= r1l) ? s[j][2] * sc : -1e30f;
                s[j][3] = (col + 1 <= r1l) ? s[j][3] * sc : -1e30f;
            }
        } else {
#pragma unroll
            for (int j = 0; j < 8; j++)
#pragma unroll
                for (int e = 0; e < 4; e++) s[j][e] *= sc;
        }

        float mx0 = -1e30f, mx1 = -1e30f;
#pragma unroll
        for (int j = 0; j < 8; j++) {
            mx0 = fmaxf(mx0, fmaxf(s[j][0], s[j][1]));
            mx1 = fmaxf(mx1, fmaxf(s[j][2], s[j][3]));
        }
        mx0 = fmaxf(mx0, __shfl_xor_sync(0xffffffffu, mx0, 1));
        mx0 = fmaxf(mx0, __shfl_xor_sync(0xffffffffu, mx0, 2));
        mx1 = fmaxf(mx1, __shfl_xor_sync(0xffffffffu, mx1, 1));
        mx1 = fmaxf(mx1, __shfl_xor_sync(0xffffffffu, mx1, 2));

        const float nm0 = fmaxf(mr0, mx0), nm1 = fmaxf(mr1, mx1);
        const float al0 = __expf(mr0 - nm0), al1 = __expf(mr1 - nm1);
        mr0 = nm0; mr1 = nm1;

        // exp -> P fragments in registers (no smem round trip)
        uint32_t pfrag[4][4];
        float ls0 = 0.f, ls1 = 0.f;
#pragma unroll
        for (int j = 0; j < 8; j++) {
            uint32_t h01 = f2h2(__expf(s[j][0] - nm0), __expf(s[j][1] - nm0));
            uint32_t h23 = f2h2(__expf(s[j][2] - nm1), __expf(s[j][3] - nm1));
            float2 f01 = __half22float2(*(__half2*)&h01);
            float2 f23 = __half22float2(*(__half2*)&h23);
            ls0 += f01.x + f01.y;
            ls1 += f23.x + f23.y;
            pfrag[j >> 1][(j & 1) * 2 + 0] = h01;
            pfrag[j >> 1][(j & 1) * 2 + 1] = h23;
        }
        ls0 += __shfl_xor_sync(0xffffffffu, ls0, 1);
        ls0 += __shfl_xor_sync(0xffffffffu, ls0, 2);
        ls1 += __shfl_xor_sync(0xffffffffu, ls1, 1);
        ls1 += __shfl_xor_sync(0xffffffffu, ls1, 2);
        l0 = l0 * al0 + ls0;
        l1 = l1 * al1 + ls1;

#pragma unroll
        for (int j = 0; j < 8; j++) {
            o[j][0] *= al0; o[j][1] *= al0;
            o[j][2] *= al1; o[j][3] *= al1;
        }

        // O += P V   (V row-major, B frags via ldmatrix.trans)
#pragma unroll
        for (int t = 0; t < 4; t++) {
            uint32_t b[8][2];
#pragma unroll
            for (int q = 0; q < 4; q++)
                LDSM4T(b[2*q][0], b[2*q][1], b[2*q+1][0], b[2*q+1][1],
                       sV + v_loff + (t * 16 * SKH + q * 16) * 2);
#pragma unroll
            for (int j = 0; j < 8; j++)
                mma_fp16(o[j], pfrag[t], b[j]);
        }
    }

    // Epilogue: normalize, write [B,T,C] fp32
    const int b = bh >> 4, h = bh & 15;
    const float inv0 = 1.f / l0, inv1 = 1.f / l1;
    const int t0 = qt * 64 + m0 + r;
#pragma unroll
    for (int j = 0; j < 8; j++) {
        const int d = j * 8 + 2 * cq;
        float2 w0 = { o[j][0] * inv0, o[j][1] * inv0 };
        *(float2*)(g_Y + ((size_t)b * T_ + t0)     * C_ + h * 64 + d) = w0;
        float2 w1 = { o[j][2] * inv1, o[j][3] * inv1 };
        *(float2*)(g_Y + ((size_t)b * T_ + t0 + 8) * C_ + h * 64 + d) = w1;
    }
}

// ---------------------------------------------------------------------------
extern "C" void kernel_launch(void* const* d_in, const int* in_sizes, int n_in,
                              void* d_out, int out_size)
{
    const float* X  = (const float*)d_in[0];
    const float* Wq = (const float*)d_in[1];
    const float* Wk = (const float*)d_in[2];
    const float* Wv = (const float*)d_in[3];
    const float* Wo = (const float*)d_in[4];
    const float* bo = (const float*)d_in[5];
    float* out = (float*)d_out;

    dim3 ggrid(NK_ / 128, M_ / 128);   // (8, 64)

    gemm_fp16<<<ggrid, 256>>>(X, -1, Wq, nullptr, 0, nullptr, 1);
    gemm_fp16<<<ggrid, 256>>>(X, -1, Wk, nullptr, 1, nullptr, 1);
    gemm_fp16<<<ggrid, 256>>>(X, -1, Wv, nullptr, 2, nullptr, 1);

    attn_fp16<<<dim3(T_ / 64, B_ * H_), 128>>>();

    gemm_fp16<<<ggrid, 256>>>(nullptr, 3, Wo, out, -1, bo, 2);
}

// round 13
// speedup vs baseline: 8.1757x; 1.3967x over previous
#include <cuda_runtime.h>
#include <cuda_fp16.h>
#include <cstdint>

#define B_  4
#define T_  2048
#define C_  1024
#define H_  16
#define D_  64
#define M_  (B_ * T_)
#define NK_ 1024

// fp16 operands / activations (device globals: referenced ONLY in device code)
__device__ __align__(256) __half g_Xh[(size_t)M_ * C_];
__device__ __align__(256) __half g_Wh[4][(size_t)C_ * C_];
__device__ __align__(256) __half g_Qh[(size_t)B_ * H_ * T_ * D_];
__device__ __align__(256) __half g_Kh[(size_t)B_ * H_ * T_ * D_];
__device__ __align__(256) __half g_Vh[(size_t)B_ * H_ * T_ * D_];
__device__ __align__(256) __half g_Yh[(size_t)M_ * C_];

__device__ __forceinline__ uint32_t smem_u32(const void* p) {
    uint32_t a;
    asm("{ .reg .u64 t; cvta.to.shared.u64 t, %1; cvt.u32.u64 %0, t; }"
        : "=r"(a) : "l"(p));
    return a;
}
__device__ __forceinline__ uint32_t f2h2(float x, float y) {
    __half2 h = __floats2half2_rn(x, y);
    return *(uint32_t*)&h;
}
__device__ __forceinline__ void mma_fp16(float c[4], const uint32_t a[4], const uint32_t b[2]) {
    asm volatile(
        "mma.sync.aligned.m16n8k16.row.col.f32.f16.f16.f32 "
        "{%0,%1,%2,%3}, {%4,%5,%6,%7}, {%8,%9}, {%0,%1,%2,%3};"
        : "+f"(c[0]), "+f"(c[1]), "+f"(c[2]), "+f"(c[3])
        : "r"(a[0]), "r"(a[1]), "r"(a[2]), "r"(a[3]), "r"(b[0]), "r"(b[1]));
}
#define LDSM4(r0, r1, r2, r3, a) \
    asm volatile("ldmatrix.sync.aligned.m8n8.x4.shared.b16 {%0,%1,%2,%3}, [%4];" \
        : "=r"(r0), "=r"(r1), "=r"(r2), "=r"(r3) : "r"(a))
#define LDSM4T(r0, r1, r2, r3, a) \
    asm volatile("ldmatrix.sync.aligned.m8n8.x4.trans.shared.b16 {%0,%1,%2,%3}, [%4];" \
        : "=r"(r0), "=r"(r1), "=r"(r2), "=r"(r3) : "r"(a))
#define CPA16(dst, src) \
    asm volatile("cp.async.cg.shared.global [%0], [%1], 16;" :: "r"(dst), "l"(src))
#define CP_COMMIT() asm volatile("cp.async.commit_group;")
#define CP_WAIT1()  asm volatile("cp.async.wait_group 1;")

// ---------------------------------------------------------------------------
// fp32 -> fp16 convert. dsel: 0 -> g_Xh, 1..4 -> g_Wh[dsel-1]
// ---------------------------------------------------------------------------
__global__ __launch_bounds__(256)
void convert_h(const float* __restrict__ src, int dsel, int n)
{
    __half* dst = (dsel == 0) ? g_Xh : g_Wh[dsel - 1];
    int i = (blockIdx.x * 256 + threadIdx.x) * 4;
    if (i >= n) return;
    float4 v = *(const float4*)(src + i);
    *(uint2*)(dst + i) = make_uint2(f2h2(v.x, v.y), f2h2(v.z, v.w));
}

// ---------------------------------------------------------------------------
// HGEMM-NT: out[m][n] = sum_k A[m][k]*W[n][k] (+bias). A, W fp16 globals.
// Block 128x128, warp 32x64, BK=32, cp.async double buffer, ldmatrix.
// a_sel: 0 -> g_Xh, 1 -> g_Yh.  w_sel: index into g_Wh.
// mode 1: half out permuted [B,H,T,D] (out_sel 0/1/2 -> g_Qh/g_Kh/g_Vh);
// mode 2: float out_f + bias.
// ---------------------------------------------------------------------------
#define PADG 40   // 80 B row stride: 16B-aligned, 20r mod 32 conflict-free

__global__ __launch_bounds__(256, 2)
void gemm_h(int a_sel, int w_sel, float* __restrict__ out_f, int out_sel,
            const float* __restrict__ bias, int mode)
{
    __shared__ __half As[2][128 * PADG];
    __shared__ __half Bs[2][128 * PADG];

    const __half* A = a_sel ? g_Yh : g_Xh;
    const __half* W = g_Wh[w_sel];
    __half* out_h = (out_sel == 0) ? g_Qh : (out_sel == 1 ? g_Kh : g_Vh);

    const int tid  = threadIdx.x;
    const int lane = tid & 31, wid = tid >> 5;
    const int wm = (wid >> 1) * 32;
    const int wn = (wid & 1) * 64;
    const int r = lane >> 2, cq = lane & 3;

    const int bm = blockIdx.y, bn = blockIdx.x;
    const __half* Ap = A + (size_t)(bm * 128) * NK_;
    const __half* Bp = W + (size_t)(bn * 128) * NK_;

    const int lrow = tid >> 2;          // 0..63: rows lrow, lrow+64
    const int lcol = (tid & 3) * 8;     // 0,8,16,24

    const uint32_t sA = smem_u32(As), sB = smem_u32(Bs);
    const int eL = lane & 7;
    const uint32_t a_loff = ((wm + 8 * ((lane >> 3) & 1) + eL) * PADG + 8 * (lane >> 4)) * 2;
    const uint32_t b_loff = ((wn + 8 * (lane >> 4) + eL) * PADG + 8 * ((lane >> 3) & 1)) * 2;

    float c[2][8][4];
#pragma unroll
    for (int i = 0; i < 2; i++)
#pragma unroll
        for (int j = 0; j < 8; j++)
#pragma unroll
            for (int e = 0; e < 4; e++) c[i][j][e] = 0.f;

    const int NT = NK_ / 32;   // 32 stages

#pragma unroll
    for (int st = 0; st < 2; st++) {
#pragma unroll
        for (int u = 0; u < 2; u++) {
            const int row = lrow + u * 64;
            CPA16(sA + (st * 128 * PADG + row * PADG + lcol) * 2,
                  Ap + (size_t)row * NK_ + st * 32 + lcol);
            CPA16(sB + (st * 128 * PADG + row * PADG + lcol) * 2,
                  Bp + (size_t)row * NK_ + st * 32 + lcol);
        }
        CP_COMMIT();
    }

    for (int kb = 0; kb < NT; kb++) {
        CP_WAIT1();
        __syncthreads();
        const int cur = kb & 1;
        const uint32_t abuf = sA + cur * 128 * PADG * 2;
        const uint32_t bbuf = sB + cur * 128 * PADG * 2;
#pragma unroll
        for (int t = 0; t < 2; t++) {
            uint32_t a[2][4], b[8][2];
#pragma unroll
            for (int i = 0; i < 2; i++)
                LDSM4(a[i][0], a[i][1], a[i][2], a[i][3],
                      abuf + a_loff + (i * 16 * PADG + t * 16) * 2);
#pragma unroll
            for (int q = 0; q < 4; q++)
                LDSM4(b[2*q][0], b[2*q][1], b[2*q+1][0], b[2*q+1][1],
                      bbuf + b_loff + (q * 16 * PADG + t * 16) * 2);
#pragma unroll
            for (int i = 0; i < 2; i++)
#pragma unroll
                for (int j = 0; j < 8; j++)
                    mma_fp16(c[i][j], a[i], b[j]);
        }
        __syncthreads();
        if (kb + 2 < NT) {
#pragma unroll
            for (int u = 0; u < 2; u++) {
                const int row = lrow + u * 64;
                CPA16(sA + (cur * 128 * PADG + row * PADG + lcol) * 2,
                      Ap + (size_t)row * NK_ + (kb + 2) * 32 + lcol);
                CPA16(sB + (cur * 128 * PADG + row * PADG + lcol) * 2,
                      Bp + (size_t)row * NK_ + (kb + 2) * 32 + lcol);
            }
        }
        CP_COMMIT();
    }

    // Epilogue
#pragma unroll
    for (int i = 0; i < 2; i++) {
#pragma unroll
        for (int j = 0; j < 8; j++) {
            const int row = bm * 128 + wm + 16 * i + r;
            const int col = bn * 128 + wn + 8 * j + 2 * cq;
            float v0 = c[i][j][0], v1 = c[i][j][1];
            float v2 = c[i][j][2], v3 = c[i][j][3];
            if (mode == 1) {
                const int h = col >> 6, d = col & 63;
                const int bb = row >> 11, t = row & 2047;
                *(uint32_t*)(out_h + (((size_t)bb * H_ + h) * T_ + t) * D_ + d)
                    = f2h2(v0, v1);
                *(uint32_t*)(out_h + (((size_t)bb * H_ + h) * T_ + (t + 8)) * D_ + d)
                    = f2h2(v2, v3);
            } else {
                float b0 = bias[col], b1 = bias[col + 1];
                float2 p0 = { v0 + b0, v1 + b1 };
                *(float2*)(out_f + (size_t)row * NK_ + col) = p0;
                float2 p1 = { v2 + b0, v3 + b1 };
                *(float2*)(out_f + (size_t)(row + 8) * NK_ + col) = p1;
            }
        }
    }
}

// ---------------------------------------------------------------------------
// FP16 flash attention. Block = 128 queries of one (b,h), 8 warps x 16 rows.
// cp.async double-buffered K/V (64-key tiles), Q + P in registers.
// SKH=88: 176 B row stride (16B-aligned), 44r mod 32 distinct -> conflict-free.
// ---------------------------------------------------------------------------
#define SKH 88

__global__ __launch_bounds__(256, 2)
void attn_h(void)
{
    __shared__ __half Kh[2][64 * SKH];
    __shared__ __half Vh[2][64 * SKH];

    const int tid = threadIdx.x, lane = tid & 31, wid = tid >> 5;
    const int qtile = (gridDim.x - 1) - blockIdx.x;   // longest first
    const int bh = blockIdx.y;
    const int q0 = qtile * 128;
    const int m0 = wid * 16;
    const int r = lane >> 2, cq = lane & 3;

    const int eL = lane & 7;
    const uint32_t sK = smem_u32(Kh), sV = smem_u32(Vh);
    const uint32_t k_loff = ((8 * (lane >> 4) + eL) * SKH + 8 * ((lane >> 3) & 1)) * 2;
    const uint32_t v_loff = ((8 * ((lane >> 3) & 1) + eL) * SKH + 8 * (lane >> 4)) * 2;

    // Q fragments in registers (direct LDG, half)
    const __half* Qb = g_Qh + ((size_t)bh * T_ + q0 + m0) * D_;
    uint32_t qa[4][4];
#pragma unroll
    for (int t = 0; t < 4; t++) {
        qa[t][0] = *(const uint32_t*)(Qb + (r)     * D_ + 16 * t + 2 * cq);
        qa[t][1] = *(const uint32_t*)(Qb + (r + 8) * D_ + 16 * t + 2 * cq);
        qa[t][2] = *(const uint32_t*)(Qb + (r)     * D_ + 16 * t + 8 + 2 * cq);
        qa[t][3] = *(const uint32_t*)(Qb + (r + 8) * D_ + 16 * t + 8 + 2 * cq);
    }

    float o[8][4];
#pragma unroll
    for (int j = 0; j < 8; j++)
#pragma unroll
        for (int e = 0; e < 4; e++) o[j][e] = 0.f;
    float mr0 = -1e30f, mr1 = -1e30f, l0 = 0.f, l1 = 0.f;

    const __half* Kbh = g_Kh + (size_t)bh * T_ * D_;
    const __half* Vbh = g_Vh + (size_t)bh * T_ * D_;
    const int ntiles = (q0 + 128) / 64;

#pragma unroll
    for (int st = 0; st < 2; st++) {
        if (st < ntiles) {
#pragma unroll
            for (int u = 0; u < 2; u++) {
                int cch = tid + u * 256;
                int row = cch >> 3, col8 = (cch & 7) * 8;
                CPA16(sK + (st * 64 * SKH + row * SKH + col8) * 2,
                      Kbh + (size_t)(st * 64 + row) * D_ + col8);
                CPA16(sV + (st * 64 * SKH + row * SKH + col8) * 2,
                      Vbh + (size_t)(st * 64 + row) * D_ + col8);
            }
        }
        CP_COMMIT();
    }

    for (int kt = 0; kt < ntiles; kt++) {
        CP_WAIT1();
        __syncthreads();
        const int cur = kt & 1;
        const int s0 = kt * 64;
        const uint32_t kbuf = sK + cur * 64 * SKH * 2;
        const uint32_t vbuf = sV + cur * 64 * SKH * 2;

        if (s0 <= q0 + m0 + 15) {   // tile not fully masked for this warp
            float s[8][4];
#pragma unroll
            for (int j = 0; j < 8; j++)
#pragma unroll
                for (int e = 0; e < 4; e++) s[j][e] = 0.f;
#pragma unroll
            for (int t = 0; t < 4; t++) {
                uint32_t b[8][2];
#pragma unroll
                for (int q = 0; q < 4; q++)
                    LDSM4(b[2*q][0], b[2*q][1], b[2*q+1][0], b[2*q+1][1],
                          kbuf + k_loff + (q * 16 * SKH + t * 16) * 2);
#pragma unroll
                for (int j = 0; j < 8; j++)
                    mma_fp16(s[j], qa[t], b[j]);
            }

            const float sc = 0.125f;
            if (s0 + 63 > q0 + m0) {
                const int r0l = q0 + m0 + r, r1l = r0l + 8;
#pragma unroll
                for (int j = 0; j < 8; j++) {
                    const int col = s0 + j * 8 + 2 * cq;
                    s[j][0] = (col     <= r0l) ? s[j][0] * sc : -1e30f;
                    s[j][1] = (col + 1 <= r0l) ? s[j][1] * sc : -1e30f;
                    s[j][2] = (col     <= r1l) ? s[j][2] * sc : -1e30f;
                    s[j][3] = (col + 1 <= r1l) ? s[j][3] * sc : -1e30f;
                }
            } else {
#pragma unroll
                for (int j = 0; j < 8; j++)
#pragma unroll
                    for (int e = 0; e < 4; e++) s[j][e] *= sc;
            }

            float mx0 = -1e30f, mx1 = -1e30f;
#pragma unroll
            for (int j = 0; j < 8; j++) {
                mx0 = fmaxf(mx0, fmaxf(s[j][0], s[j][1]));
                mx1 = fmaxf(mx1, fmaxf(s[j][2], s[j][3]));
            }
            mx0 = fmaxf(mx0, __shfl_xor_sync(0xffffffffu, mx0, 1));
            mx0 = fmaxf(mx0, __shfl_xor_sync(0xffffffffu, mx0, 2));
            mx1 = fmaxf(mx1, __shfl_xor_sync(0xffffffffu, mx1, 1));
            mx1 = fmaxf(mx1, __shfl_xor_sync(0xffffffffu, mx1, 2));

            const float nm0 = fmaxf(mr0, mx0), nm1 = fmaxf(mr1, mx1);
            const float al0 = __expf(mr0 - nm0), al1 = __expf(mr1 - nm1);
            mr0 = nm0; mr1 = nm1;

            uint32_t pfrag[4][4];
            float ls0 = 0.f, ls1 = 0.f;
#pragma unroll
            for (int j = 0; j < 8; j++) {
                uint32_t h01 = f2h2(__expf(s[j][0] - nm0), __expf(s[j][1] - nm0));
                uint32_t h23 = f2h2(__expf(s[j][2] - nm1), __expf(s[j][3] - nm1));
                float2 f01 = __half22float2(*(__half2*)&h01);
                float2 f23 = __half22float2(*(__half2*)&h23);
                ls0 += f01.x + f01.y;
                ls1 += f23.x + f23.y;
                pfrag[j >> 1][(j & 1) * 2 + 0] = h01;
                pfrag[j >> 1][(j & 1) * 2 + 1] = h23;
            }
            ls0 += __shfl_xor_sync(0xffffffffu, ls0, 1);
            ls0 += __shfl_xor_sync(0xffffffffu, ls0, 2);
            ls1 += __shfl_xor_sync(0xffffffffu, ls1, 1);
            ls1 += __shfl_xor_sync(0xffffffffu, ls1, 2);
            l0 = l0 * al0 + ls0;
            l1 = l1 * al1 + ls1;

#pragma unroll
            for (int j = 0; j < 8; j++) {
                o[j][0] *= al0; o[j][1] *= al0;
                o[j][2] *= al1; o[j][3] *= al1;
            }

#pragma unroll
            for (int t = 0; t < 4; t++) {
                uint32_t b[8][2];
#pragma unroll
                for (int q = 0; q < 4; q++)
                    LDSM4T(b[2*q][0], b[2*q][1], b[2*q+1][0], b[2*q+1][1],
                           vbuf + v_loff + (t * 16 * SKH + q * 16) * 2);
#pragma unroll
                for (int j = 0; j < 8; j++)
                    mma_fp16(o[j], pfrag[t], b[j]);
            }
        }

        __syncthreads();
        if (kt + 2 < ntiles) {
            const int s2 = (kt + 2) * 64;
#pragma unroll
            for (int u = 0; u < 2; u++) {
                int cch = tid + u * 256;
                int row = cch >> 3, col8 = (cch & 7) * 8;
                CPA16(sK + (cur * 64 * SKH + row * SKH + col8) * 2,
                      Kbh + (size_t)(s2 + row) * D_ + col8);
                CPA16(sV + (cur * 64 * SKH + row * SKH + col8) * 2,
                      Vbh + (size_t)(s2 + row) * D_ + col8);
            }
        }
        CP_COMMIT();
    }

    // Epilogue: normalize, write [B,T,C] half
    const int b = bh >> 4, h = bh & 15;
    const float inv0 = 1.f / l0, inv1 = 1.f / l1;
    const int t0 = q0 + m0 + r;
#pragma unroll
    for (int j = 0; j < 8; j++) {
        const int d = j * 8 + 2 * cq;
        *(uint32_t*)(g_Yh + ((size_t)b * T_ + t0)     * C_ + h * 64 + d)
            = f2h2(o[j][0] * inv0, o[j][1] * inv0);
        *(uint32_t*)(g_Yh + ((size_t)b * T_ + t0 + 8) * C_ + h * 64 + d)
            = f2h2(o[j][2] * inv1, o[j][3] * inv1);
    }
}

// ---------------------------------------------------------------------------
extern "C" void kernel_launch(void* const* d_in, const int* in_sizes, int n_in,
                              void* d_out, int out_size)
{
    const float* X  = (const float*)d_in[0];
    const float* Wq = (const float*)d_in[1];
    const float* Wk = (const float*)d_in[2];
    const float* Wv = (const float*)d_in[3];
    const float* Wo = (const float*)d_in[4];
    const float* bo = (const float*)d_in[5];
    float* out = (float*)d_out;

    const int nX = M_ * C_;
    const int nW = C_ * C_;

    convert_h<<<nX / 1024, 256>>>(X,  0, nX);
    convert_h<<<nW / 1024, 256>>>(Wq, 1, nW);
    convert_h<<<nW / 1024, 256>>>(Wk, 2, nW);
    convert_h<<<nW / 1024, 256>>>(Wv, 3, nW);
    convert_h<<<nW / 1024, 256>>>(Wo, 4, nW);

    dim3 ggrid(NK_ / 128, M_ / 128);   // (8, 64)
    gemm_h<<<ggrid, 256>>>(0, 0, nullptr, 0, nullptr, 1);   // Q
    gemm_h<<<ggrid, 256>>>(0, 1, nullptr, 1, nullptr, 1);   // K
    gemm_h<<<ggrid, 256>>>(0, 2, nullptr, 2, nullptr, 1);   // V

    attn_h<<<dim3(T_ / 128, B_ * H_), 256>>>();

    gemm_h<<<ggrid, 256>>>(1, 3, out, -1, bo, 2);           // O projection
}

// round 15
// speedup vs baseline: 8.7147x; 1.0659x over previous
#include <cuda_runtime.h>
#include <cuda_fp16.h>
#include <cstdint>

#define B_  4
#define T_  2048
#define C_  1024
#define H_  16
#define D_  64
#define M_  (B_ * T_)
#define NK_ 1024

// fp16 operands / activations (device globals: referenced ONLY in device code)
__device__ __align__(256) __half g_Xh[(size_t)M_ * C_];
__device__ __align__(256) __half g_Wh[4][(size_t)C_ * C_];
__device__ __align__(256) __half g_Qh[(size_t)B_ * H_ * T_ * D_];
__device__ __align__(256) __half g_Kh[(size_t)B_ * H_ * T_ * D_];
__device__ __align__(256) __half g_Vh[(size_t)B_ * H_ * T_ * D_];
__device__ __align__(256) __half g_Yh[(size_t)M_ * C_];

__device__ __forceinline__ uint32_t smem_u32(const void* p) {
    uint32_t a;
    asm("{ .reg .u64 t; cvta.to.shared.u64 t, %1; cvt.u32.u64 %0, t; }"
        : "=r"(a) : "l"(p));
    return a;
}
__device__ __forceinline__ uint32_t f2h2(float x, float y) {
    __half2 h = __floats2half2_rn(x, y);
    return *(uint32_t*)&h;
}
__device__ __forceinline__ void mma_fp16(float c[4], const uint32_t a[4], const uint32_t b[2]) {
    asm volatile(
        "mma.sync.aligned.m16n8k16.row.col.f32.f16.f16.f32 "
        "{%0,%1,%2,%3}, {%4,%5,%6,%7}, {%8,%9}, {%0,%1,%2,%3};"
        : "+f"(c[0]), "+f"(c[1]), "+f"(c[2]), "+f"(c[3])
        : "r"(a[0]), "r"(a[1]), "r"(a[2]), "r"(a[3]), "r"(b[0]), "r"(b[1]));
}
#define LDSM4(r0, r1, r2, r3, a) \
    asm volatile("ldmatrix.sync.aligned.m8n8.x4.shared.b16 {%0,%1,%2,%3}, [%4];" \
        : "=r"(r0), "=r"(r1), "=r"(r2), "=r"(r3) : "r"(a))
#define LDSM4T(r0, r1, r2, r3, a) \
    asm volatile("ldmatrix.sync.aligned.m8n8.x4.trans.shared.b16 {%0,%1,%2,%3}, [%4];" \
        : "=r"(r0), "=r"(r1), "=r"(r2), "=r"(r3) : "r"(a))
#define CPA16(dst, src) \
    asm volatile("cp.async.cg.shared.global [%0], [%1], 16;" :: "r"(dst), "l"(src))
#define CP_COMMIT() asm volatile("cp.async.commit_group;")
#define CP_WAIT1()  asm volatile("cp.async.wait_group 1;")

// ---------------------------------------------------------------------------
// Fused fp32 -> fp16 convert: X then W0..W3, one launch.
// ---------------------------------------------------------------------------
#define NXE (M_ * C_)        // 8388608
#define NWE (C_ * C_)        // 1048576 = 2^20

__global__ __launch_bounds__(256)
void convert_all(const float* __restrict__ X,  const float* __restrict__ Wq,
                 const float* __restrict__ Wk, const float* __restrict__ Wv,
                 const float* __restrict__ Wo)
{
    int i = (blockIdx.x * 256 + threadIdx.x) * 4;
    const float* src;
    __half* dst;
    int off;
    if (i < NXE) {
        src = X; dst = g_Xh; off = i;
    } else {
        int j = i - NXE;
        int w = j >> 20;
        off = j & (NWE - 1);
        src = (w == 0) ? Wq : (w == 1) ? Wk : (w == 2) ? Wv : Wo;
        dst = g_Wh[w];
    }
    float4 v = *(const float4*)(src + off);
    *(uint2*)(dst + off) = make_uint2(f2h2(v.x, v.y), f2h2(v.z, v.w));
}

// ---------------------------------------------------------------------------
// HGEMM-NT: out[m][n] = sum_k A[m][k]*W[n][k] (+bias). 3-stage cp.async ring,
// ONE __syncthreads per k-step. Block 128x128, warp 32x64, BK=32.
// mode 1: QKV (blockIdx.z selects weight + output, permuted [B,H,T,D] half)
// mode 2: O-projection (g_Yh @ g_Wh[3] + bias -> float out)
// ---------------------------------------------------------------------------
#define PADG 40                                // 80 B row stride
#define G_STG (128 * PADG * 2)                 // stage bytes per array: 10240
#define GEMM_SMEM (2 * 3 * G_STG)              // 61440 B dynamic

__global__ __launch_bounds__(256, 2)
void gemm_h(float* __restrict__ out_f, const float* __restrict__ bias, int mode)
{
    extern __shared__ __align__(16) char dsm[];
    __half* As = (__half*)dsm;                 // 3 stages
    __half* Bs = As + 3 * 128 * PADG;

    const int wsel = (mode == 1) ? blockIdx.z : 3;
    const __half* A = (mode == 1) ? g_Xh : g_Yh;
    const __half* W = g_Wh[wsel];
    __half* out_h = (wsel == 0) ? g_Qh : (wsel == 1 ? g_Kh : g_Vh);

    const int tid  = threadIdx.x;
    const int lane = tid & 31, wid = tid >> 5;
    const int wm = (wid >> 1) * 32;
    const int wn = (wid & 1) * 64;
    const int r = lane >> 2, cq = lane & 3;

    const int bm = blockIdx.y, bn = blockIdx.x;
    const __half* Ap = A + (size_t)(bm * 128) * NK_;
    const __half* Bp = W + (size_t)(bn * 128) * NK_;

    const int lrow = tid >> 2;          // 0..63: rows lrow, lrow+64
    const int lcol = (tid & 3) * 8;     // 0,8,16,24

    const uint32_t sA = smem_u32(As), sB = smem_u32(Bs);
    const int eL = lane & 7;
    const uint32_t a_loff = ((wm + 8 * ((lane >> 3) & 1) + eL) * PADG + 8 * (lane >> 4)) * 2;
    const uint32_t b_loff = ((wn + 8 * (lane >> 4) + eL) * PADG + 8 * ((lane >> 3) & 1)) * 2;

    float c[2][8][4];
#pragma unroll
    for (int i = 0; i < 2; i++)
#pragma unroll
        for (int j = 0; j < 8; j++)
#pragma unroll
            for (int e = 0; e < 4; e++) c[i][j][e] = 0.f;

    const int NT = NK_ / 32;   // 32 k-steps

    // prologue: stages 0, 1
#pragma unroll
    for (int st = 0; st < 2; st++) {
#pragma unroll
        for (int u = 0; u < 2; u++) {
            const int row = lrow + u * 64;
            CPA16(sA + st * G_STG + (row * PADG + lcol) * 2,
                  Ap + (size_t)row * NK_ + st * 32 + lcol);
            CPA16(sB + st * G_STG + (row * PADG + lcol) * 2,
                  Bp + (size_t)row * NK_ + st * 32 + lcol);
        }
        CP_COMMIT();
    }

    int cur = 0, nxt = 2;   // kb%3, (kb+2)%3
    for (int kb = 0; kb < NT; kb++) {
        CP_WAIT1();
        __syncthreads();
        if (kb + 2 < NT) {
#pragma unroll
            for (int u = 0; u < 2; u++) {
                const int row = lrow + u * 64;
                CPA16(sA + nxt * G_STG + (row * PADG + lcol) * 2,
                      Ap + (size_t)row * NK_ + (kb + 2) * 32 + lcol);
                CPA16(sB + nxt * G_STG + (row * PADG + lcol) * 2,
                      Bp + (size_t)row * NK_ + (kb + 2) * 32 + lcol);
            }
        }
        CP_COMMIT();

        const uint32_t abuf = sA + cur * G_STG;
        const uint32_t bbuf = sB + cur * G_STG;
#pragma unroll
        for (int t = 0; t < 2; t++) {
            uint32_t a[2][4], b[8][2];
#pragma unroll
            for (int i = 0; i < 2; i++)
                LDSM4(a[i][0], a[i][1], a[i][2], a[i][3],
                      abuf + a_loff + (i * 16 * PADG + t * 16) * 2);
#pragma unroll
            for (int q = 0; q < 4; q++)
                LDSM4(b[2*q][0], b[2*q][1], b[2*q+1][0], b[2*q+1][1],
                      bbuf + b_loff + (q * 16 * PADG + t * 16) * 2);
#pragma unroll
            for (int i = 0; i < 2; i++)
#pragma unroll
                for (int j = 0; j < 8; j++)
                    mma_fp16(c[i][j], a[i], b[j]);
        }
        cur = (cur == 2) ? 0 : cur + 1;
        nxt = (nxt == 2) ? 0 : nxt + 1;
    }

    // Epilogue
#pragma unroll
    for (int i = 0; i < 2; i++) {
#pragma unroll
        for (int j = 0; j < 8; j++) {
            const int row = bm * 128 + wm + 16 * i + r;
            const int col = bn * 128 + wn + 8 * j + 2 * cq;
            float v0 = c[i][j][0], v1 = c[i][j][1];
            float v2 = c[i][j][2], v3 = c[i][j][3];
            if (mode == 1) {
                const int h = col >> 6, d = col & 63;
                const int bb = row >> 11, t = row & 2047;
                *(uint32_t*)(out_h + (((size_t)bb * H_ + h) * T_ + t) * D_ + d)
                    = f2h2(v0, v1);
                *(uint32_t*)(out_h + (((size_t)bb * H_ + h) * T_ + (t + 8)) * D_ + d)
                    = f2h2(v2, v3);
            } else {
                float b0 = bias[col], b1 = bias[col + 1];
                float2 p0 = { v0 + b0, v1 + b1 };
                *(float2*)(out_f + (size_t)row * NK_ + col) = p0;
                float2 p1 = { v2 + b0, v3 + b1 };
                *(float2*)(out_f + (size_t)(row + 8) * NK_ + col) = p1;
            }
        }
    }
}

// ---------------------------------------------------------------------------
// FP16 flash attention. Block = 128 queries of one (b,h), 8 warps x 16 rows.
// 3-stage cp.async K/V ring, ONE sync per tile. Q + P in registers.
// SKH=88: 176 B row stride (16B-aligned), 44r mod 32 distinct -> conflict-free.
// ---------------------------------------------------------------------------
#define SKH 88
#define A_STG (64 * SKH * 2)                   // stage bytes per array: 11264
#define ATT_SMEM (2 * 3 * A_STG)               // 67584 B dynamic

__global__ __launch_bounds__(256, 2)
void attn_h(void)
{
    extern __shared__ __align__(16) char dsm[];
    __half* KhB = (__half*)dsm;                // 3 stages
    __half* VhB = KhB + 3 * 64 * SKH;

    const int tid = threadIdx.x, lane = tid & 31, wid = tid >> 5;
    const int qtile = (gridDim.x - 1) - blockIdx.x;   // longest first
    const int bh = blockIdx.y;
    const int q0 = qtile * 128;
    const int m0 = wid * 16;
    const int r = lane >> 2, cq = lane & 3;

    const int eL = lane & 7;
    const uint32_t sK = smem_u32(KhB), sV = smem_u32(VhB);
    const uint32_t k_loff = ((8 * (lane >> 4) + eL) * SKH + 8 * ((lane >> 3) & 1)) * 2;
    const uint32_t v_loff = ((8 * ((lane >> 3) & 1) + eL) * SKH + 8 * (lane >> 4)) * 2;

    // Q fragments in registers (direct LDG, half)
    const __half* Qb = g_Qh + ((size_t)bh * T_ + q0 + m0) * D_;
    uint32_t qa[4][4];
#pragma unroll
    for (int t = 0; t < 4; t++) {
        qa[t][0] = *(const uint32_t*)(Qb + (r)     * D_ + 16 * t + 2 * cq);
        qa[t][1] = *(const uint32_t*)(Qb + (r + 8) * D_ + 16 * t + 2 * cq);
        qa[t][2] = *(const uint32_t*)(Qb + (r)     * D_ + 16 * t + 8 + 2 * cq);
        qa[t][3] = *(const uint32_t*)(Qb + (r + 8) * D_ + 16 * t + 8 + 2 * cq);
    }

    float o[8][4];
#pragma unroll
    for (int j = 0; j < 8; j++)
#pragma unroll
        for (int e = 0; e < 4; e++) o[j][e] = 0.f;
    float mr0 = -1e30f, mr1 = -1e30f, l0 = 0.f, l1 = 0.f;

    const __half* Kbh = g_Kh + (size_t)bh * T_ * D_;
    const __half* Vbh = g_Vh + (size_t)bh * T_ * D_;
    const int ntiles = (q0 + 128) / 64;

    // prologue: tiles 0, 1
#pragma unroll
    for (int st = 0; st < 2; st++) {
        if (st < ntiles) {
#pragma unroll
            for (int u = 0; u < 2; u++) {
                int cch = tid + u * 256;
                int row = cch >> 3, col8 = (cch & 7) * 8;
                CPA16(sK + st * A_STG + (row * SKH + col8) * 2,
                      Kbh + (size_t)(st * 64 + row) * D_ + col8);
                CPA16(sV + st * A_STG + (row * SKH + col8) * 2,
                      Vbh + (size_t)(st * 64 + row) * D_ + col8);
            }
        }
        CP_COMMIT();
    }

    int cur = 0, nxt = 2;
    for (int kt = 0; kt < ntiles; kt++) {
        CP_WAIT1();
        __syncthreads();
        if (kt + 2 < ntiles) {
            const int s2 = (kt + 2) * 64;
#pragma unroll
            for (int u = 0; u < 2; u++) {
                int cch = tid + u * 256;
                int row = cch >> 3, col8 = (cch & 7) * 8;
                CPA16(sK + nxt * A_STG + (row * SKH + col8) * 2,
                      Kbh + (size_t)(s2 + row) * D_ + col8);
                CPA16(sV + nxt * A_STG + (row * SKH + col8) * 2,
                      Vbh + (size_t)(s2 + row) * D_ + col8);
            }
        }
        CP_COMMIT();

        const int s0 = kt * 64;
        const uint32_t kbuf = sK + cur * A_STG;
        const uint32_t vbuf = sV + cur * A_STG;

        if (s0 <= q0 + m0 + 15) {   // tile not fully masked for this warp
            float s[8][4];
#pragma unroll
            for (int j = 0; j < 8; j++)
#pragma unroll
                for (int e = 0; e < 4; e++) s[j][e] = 0.f;
#pragma unroll
            for (int t = 0; t < 4; t++) {
                uint32_t b[8][2];
#pragma unroll
                for (int q = 0; q < 4; q++)
                    LDSM4(b[2*q][0], b[2*q][1], b[2*q+1][0], b[2*q+1][1],
                          kbuf + k_loff + (q * 16 * SKH + t * 16) * 2);
#pragma unroll
                for (int j = 0; j < 8; j++)
                    mma_fp16(s[j], qa[t], b[j]);
            }

            const float sc = 0.125f;
            if (s0 + 63 > q0 + m0) {
                const int r0l = q0 + m0 + r, r1l = r0l + 8;
#pragma unroll
                for (int j = 0; j < 8; j++) {
                    const int col = s0 + j * 8 + 2 * cq;
                    s[j][0] = (col     <= r0l) ? s[j][0] * sc : -1e30f;
                    s[j][1] = (col + 1 <= r0l) ? s[j][1] * sc : -1e30f;
                    s[j][2] = (col     <= r1l) ? s[j][2] * sc : -1e30f;
                    s[j][3] = (col + 1 <= r1l) ? s[j][3] * sc : -1e30f;
                }
            } else {
#pragma unroll
                for (int j = 0; j < 8; j++)
#pragma unroll
                    for (int e = 0; e < 4; e++) s[j][e] *= sc;
            }

            float mx0 = -1e30f, mx1 = -1e30f;
#pragma unroll
            for (int j = 0; j < 8; j++) {
                mx0 = fmaxf(mx0, fmaxf(s[j][0], s[j][1]));
                mx1 = fmaxf(mx1, fmaxf(s[j][2], s[j][3]));
            }
            mx0 = fmaxf(mx0, __shfl_xor_sync(0xffffffffu, mx0, 1));
            mx0 = fmaxf(mx0, __shfl_xor_sync(0xffffffffu, mx0, 2));
            mx1 = fmaxf(mx1, __shfl_xor_sync(0xffffffffu, mx1, 1));
            mx1 = fmaxf(mx1, __shfl_xor_sync(0xffffffffu, mx1, 2));

            const float nm0 = fmaxf(mr0, mx0), nm1 = fmaxf(mr1, mx1);
            const float al0 = __expf(mr0 - nm0), al1 = __expf(mr1 - nm1);
            mr0 = nm0; mr1 = nm1;

            uint32_t pfrag[4][4];
            float ls0 = 0.f, ls1 = 0.f;
#pragma unroll
            for (int j = 0; j < 8; j++) {
                uint32_t h01 = f2h2(__expf(s[j][0] - nm0), __expf(s[j][1] - nm0));
                uint32_t h23 = f2h2(__expf(s[j][2] - nm1), __expf(s[j][3] - nm1));
                float2 f01 = __half22float2(*(__half2*)&h01);
                float2 f23 = __half22float2(*(__half2*)&h23);
                ls0 += f01.x + f01.y;
                ls1 += f23.x + f23.y;
                pfrag[j >> 1][(j & 1) * 2 + 0] = h01;
                pfrag[j >> 1][(j & 1) * 2 + 1] = h23;
            }
            ls0 += __shfl_xor_sync(0xffffffffu, ls0, 1);
            ls0 += __shfl_xor_sync(0xffffffffu, ls0, 2);
            ls1 += __shfl_xor_sync(0xffffffffu, ls1, 1);
            ls1 += __shfl_xor_sync(0xffffffffu, ls1, 2);
            l0 = l0 * al0 + ls0;
            l1 = l1 * al1 + ls1;

#pragma unroll
            for (int j = 0; j < 8; j++) {
                o[j][0] *= al0; o[j][1] *= al0;
                o[j][2] *= al1; o[j][3] *= al1;
            }

#pragma unroll
            for (int t = 0; t < 4; t++) {
                uint32_t b[8][2];
#pragma unroll
                for (int q = 0; q < 4; q++)
                    LDSM4T(b[2*q][0], b[2*q][1], b[2*q+1][0], b[2*q+1][1],
                           vbuf + v_loff + (t * 16 * SKH + q * 16) * 2);
#pragma unroll
                for (int j = 0; j < 8; j++)
                    mma_fp16(o[j], pfrag[t], b[j]);
            }
        }
        cur = (cur == 2) ? 0 : cur + 1;
        nxt = (nxt == 2) ? 0 : nxt + 1;
    }

    // Epilogue: normalize, write [B,T,C] half
    const int b = bh >> 4, h = bh & 15;
    const float inv0 = 1.f / l0, inv1 = 1.f / l1;
    const int t0 = q0 + m0 + r;
#pragma unroll
    for (int j = 0; j < 8; j++) {
        const int d = j * 8 + 2 * cq;
        *(uint32_t*)(g_Yh + ((size_t)b * T_ + t0)     * C_ + h * 64 + d)
            = f2h2(o[j][0] * inv0, o[j][1] * inv0);
        *(uint32_t*)(g_Yh + ((size_t)b * T_ + t0 + 8) * C_ + h * 64 + d)
            = f2h2(o[j][2] * inv1, o[j][3] * inv1);
    }
}

// ---------------------------------------------------------------------------
extern "C" void kernel_launch(void* const* d_in, const int* in_sizes, int n_in,
                              void* d_out, int out_size)
{
    const float* X  = (const float*)d_in[0];
    const float* Wq = (const float*)d_in[1];
    const float* Wk = (const float*)d_in[2];
    const float* Wv = (const float*)d_in[3];
    const float* Wo = (const float*)d_in[4];
    const float* bo = (const float*)d_in[5];
    float* out = (float*)d_out;

    cudaFuncSetAttribute(gemm_h, cudaFuncAttributeMaxDynamicSharedMemorySize, GEMM_SMEM);
    cudaFuncSetAttribute(attn_h, cudaFuncAttributeMaxDynamicSharedMemorySize, ATT_SMEM);

    const int ntotal = NXE + 4 * NWE;   // 12582912
    convert_all<<<ntotal / 1024, 256>>>(X, Wq, Wk, Wv, Wo);

    // QKV fused: gridDim.z selects weight/output
    gemm_h<<<dim3(NK_ / 128, M_ / 128, 3), 256, GEMM_SMEM>>>(nullptr, nullptr, 1);

    attn_h<<<dim3(T_ / 128, B_ * H_), 256, ATT_SMEM>>>();

    // O projection
    gemm_h<<<dim3(NK_ / 128, M_ / 128, 1), 256, GEMM_SMEM>>>(out, bo, 2);
}

// round 16
// speedup vs baseline: 8.9178x; 1.0233x over previous
#include <cuda_runtime.h>
#include <cuda_fp16.h>
#include <cstdint>

#define B_  4
#define T_  2048
#define C_  1024
#define H_  16
#define D_  64
#define M_  (B_ * T_)
#define NK_ 1024

// fp16 operands / activations (device globals: referenced ONLY in device code)
__device__ __align__(256) __half g_Xh[(size_t)M_ * C_];
__device__ __align__(256) __half g_Wh[4][(size_t)C_ * C_];
__device__ __align__(256) __half g_Qh[(size_t)B_ * H_ * T_ * D_];
__device__ __align__(256) __half g_Kh[(size_t)B_ * H_ * T_ * D_];
__device__ __align__(256) __half g_Vh[(size_t)B_ * H_ * T_ * D_];
__device__ __align__(256) __half g_Yh[(size_t)M_ * C_];

__device__ __forceinline__ uint32_t smem_u32(const void* p) {
    uint32_t a;
    asm("{ .reg .u64 t; cvta.to.shared.u64 t, %1; cvt.u32.u64 %0, t; }"
        : "=r"(a) : "l"(p));
    return a;
}
__device__ __forceinline__ uint32_t f2h2(float x, float y) {
    __half2 h = __floats2half2_rn(x, y);
    return *(uint32_t*)&h;
}
__device__ __forceinline__ void mma_fp16(float c[4], const uint32_t a[4], const uint32_t b[2]) {
    asm volatile(
        "mma.sync.aligned.m16n8k16.row.col.f32.f16.f16.f32 "
        "{%0,%1,%2,%3}, {%4,%5,%6,%7}, {%8,%9}, {%0,%1,%2,%3};"
        : "+f"(c[0]), "+f"(c[1]), "+f"(c[2]), "+f"(c[3])
        : "r"(a[0]), "r"(a[1]), "r"(a[2]), "r"(a[3]), "r"(b[0]), "r"(b[1]));
}
#define LDSM4(r0, r1, r2, r3, a) \
    asm volatile("ldmatrix.sync.aligned.m8n8.x4.shared.b16 {%0,%1,%2,%3}, [%4];" \
        : "=r"(r0), "=r"(r1), "=r"(r2), "=r"(r3) : "r"(a))
#define LDSM4T(r0, r1, r2, r3, a) \
    asm volatile("ldmatrix.sync.aligned.m8n8.x4.trans.shared.b16 {%0,%1,%2,%3}, [%4];" \
        : "=r"(r0), "=r"(r1), "=r"(r2), "=r"(r3) : "r"(a))
#define CPA16(dst, src) \
    asm volatile("cp.async.cg.shared.global [%0], [%1], 16;" :: "r"(dst), "l"(src))
#define CP_COMMIT() asm volatile("cp.async.commit_group;")
#define CP_WAIT2()  asm volatile("cp.async.wait_group 2;")
#define EX2_H2(d, s) \
    asm volatile("ex2.approx.f16x2 %0, %1;" : "=r"(d) : "r"(s))

// ---------------------------------------------------------------------------
// Fused fp32 -> fp16 convert: X then W0..W3, one launch.
// ---------------------------------------------------------------------------
#define NXE (M_ * C_)        // 8388608
#define NWE (C_ * C_)        // 1048576 = 2^20

__global__ __launch_bounds__(256)
void convert_all(const float* __restrict__ X,  const float* __restrict__ Wq,
                 const float* __restrict__ Wk, const float* __restrict__ Wv,
                 const float* __restrict__ Wo)
{
    int i = (blockIdx.x * 256 + threadIdx.x) * 4;
    const float* src;
    __half* dst;
    int off;
    if (i < NXE) {
        src = X; dst = g_Xh; off = i;
    } else {
        int j = i - NXE;
        int w = j >> 20;
        off = j & (NWE - 1);
        src = (w == 0) ? Wq : (w == 1) ? Wk : (w == 2) ? Wv : Wo;
        dst = g_Wh[w];
    }
    float4 v = *(const float4*)(src + off);
    *(uint2*)(dst + off) = make_uint2(f2h2(v.x, v.y), f2h2(v.z, v.w));
}

// ---------------------------------------------------------------------------
// HGEMM-NT: 4-stage cp.async ring (wait_group 2), ONE sync per k-step.
// Block 128x128, warp 32x64, BK=32.
// mode 1: QKV (blockIdx.z selects weight + output, permuted [B,H,T,D] half)
// mode 2: O-projection (g_Yh @ g_Wh[3] + bias -> float out)
// ---------------------------------------------------------------------------
#define PADG 40                                // 80 B row stride
#define G_STG (128 * PADG * 2)                 // stage bytes per array: 10240
#define GEMM_SMEM (2 * 4 * G_STG)              // 81920 B dynamic

__global__ __launch_bounds__(256, 2)
void gemm_h(float* __restrict__ out_f, const float* __restrict__ bias, int mode)
{
    extern __shared__ __align__(16) char dsm[];
    __half* As = (__half*)dsm;                 // 4 stages
    __half* Bs = As + 4 * 128 * PADG;

    const int wsel = (mode == 1) ? blockIdx.z : 3;
    const __half* A = (mode == 1) ? g_Xh : g_Yh;
    const __half* W = g_Wh[wsel];
    __half* out_h = (wsel == 0) ? g_Qh : (wsel == 1 ? g_Kh : g_Vh);

    const int tid  = threadIdx.x;
    const int lane = tid & 31, wid = tid >> 5;
    const int wm = (wid >> 1) * 32;
    const int wn = (wid & 1) * 64;
    const int r = lane >> 2, cq = lane & 3;

    const int bm = blockIdx.y, bn = blockIdx.x;
    const __half* Ap = A + (size_t)(bm * 128) * NK_;
    const __half* Bp = W + (size_t)(bn * 128) * NK_;

    const int lrow = tid >> 2;          // 0..63: rows lrow, lrow+64
    const int lcol = (tid & 3) * 8;     // 0,8,16,24

    const uint32_t sA = smem_u32(As), sB = smem_u32(Bs);
    const int eL = lane & 7;
    const uint32_t a_loff = ((wm + 8 * ((lane >> 3) & 1) + eL) * PADG + 8 * (lane >> 4)) * 2;
    const uint32_t b_loff = ((wn + 8 * (lane >> 4) + eL) * PADG + 8 * ((lane >> 3) & 1)) * 2;

    float c[2][8][4];
#pragma unroll
    for (int i = 0; i < 2; i++)
#pragma unroll
        for (int j = 0; j < 8; j++)
#pragma unroll
            for (int e = 0; e < 4; e++) c[i][j][e] = 0.f;

    const int NT = NK_ / 32;   // 32 k-steps

    // prologue: stages 0, 1, 2
#pragma unroll
    for (int st = 0; st < 3; st++) {
#pragma unroll
        for (int u = 0; u < 2; u++) {
            const int row = lrow + u * 64;
            CPA16(sA + st * G_STG + (row * PADG + lcol) * 2,
                  Ap + (size_t)row * NK_ + st * 32 + lcol);
            CPA16(sB + st * G_STG + (row * PADG + lcol) * 2,
                  Bp + (size_t)row * NK_ + st * 32 + lcol);
        }
        CP_COMMIT();
    }

    int cur = 0, nxt = 3;   // kb%4, (kb+3)%4
    for (int kb = 0; kb < NT; kb++) {
        CP_WAIT2();
        __syncthreads();
        if (kb + 3 < NT) {
#pragma unroll
            for (int u = 0; u < 2; u++) {
                const int row = lrow + u * 64;
                CPA16(sA + nxt * G_STG + (row * PADG + lcol) * 2,
                      Ap + (size_t)row * NK_ + (kb + 3) * 32 + lcol);
                CPA16(sB + nxt * G_STG + (row * PADG + lcol) * 2,
                      Bp + (size_t)row * NK_ + (kb + 3) * 32 + lcol);
            }
        }
        CP_COMMIT();

        const uint32_t abuf = sA + cur * G_STG;
        const uint32_t bbuf = sB + cur * G_STG;
#pragma unroll
        for (int t = 0; t < 2; t++) {
            uint32_t a[2][4], b[8][2];
#pragma unroll
            for (int i = 0; i < 2; i++)
                LDSM4(a[i][0], a[i][1], a[i][2], a[i][3],
                      abuf + a_loff + (i * 16 * PADG + t * 16) * 2);
#pragma unroll
            for (int q = 0; q < 4; q++)
                LDSM4(b[2*q][0], b[2*q][1], b[2*q+1][0], b[2*q+1][1],
                      bbuf + b_loff + (q * 16 * PADG + t * 16) * 2);
#pragma unroll
            for (int i = 0; i < 2; i++)
#pragma unroll
                for (int j = 0; j < 8; j++)
                    mma_fp16(c[i][j], a[i], b[j]);
        }
        cur = (cur == 3) ? 0 : cur + 1;
        nxt = (nxt == 3) ? 0 : nxt + 1;
    }

    // Epilogue
#pragma unroll
    for (int i = 0; i < 2; i++) {
#pragma unroll
        for (int j = 0; j < 8; j++) {
            const int row = bm * 128 + wm + 16 * i + r;
            const int col = bn * 128 + wn + 8 * j + 2 * cq;
            float v0 = c[i][j][0], v1 = c[i][j][1];
            float v2 = c[i][j][2], v3 = c[i][j][3];
            if (mode == 1) {
                const int h = col >> 6, d = col & 63;
                const int bb = row >> 11, t = row & 2047;
                *(uint32_t*)(out_h + (((size_t)bb * H_ + h) * T_ + t) * D_ + d)
                    = f2h2(v0, v1);
                *(uint32_t*)(out_h + (((size_t)bb * H_ + h) * T_ + (t + 8)) * D_ + d)
                    = f2h2(v2, v3);
            } else {
                float b0 = bias[col], b1 = bias[col + 1];
                float2 p0 = { v0 + b0, v1 + b1 };
                *(float2*)(out_f + (size_t)row * NK_ + col) = p0;
                float2 p1 = { v2 + b0, v3 + b1 };
                *(float2*)(out_f + (size_t)(row + 8) * NK_ + col) = p1;
            }
        }
    }
}

// ---------------------------------------------------------------------------
// FP16 flash attention. Block = 128 queries of one (b,h), 8 warps x 16 rows.
// 4-stage cp.async K/V ring, ONE sync per tile. Q + P in registers.
// Softmax exponentials via ex2.approx.f16x2 (2 exps / MUFU op).
// SKH=88: 176 B row stride (16B-aligned), 44r mod 32 distinct -> conflict-free.
// ---------------------------------------------------------------------------
#define SKH 88
#define A_STG (64 * SKH * 2)                   // stage bytes per array: 11264
#define ATT_SMEM (2 * 4 * A_STG)               // 90112 B dynamic

__global__ __launch_bounds__(256, 2)
void attn_h(void)
{
    extern __shared__ __align__(16) char dsm[];
    __half* KhB = (__half*)dsm;                // 4 stages
    __half* VhB = KhB + 4 * 64 * SKH;

    const int tid = threadIdx.x, lane = tid & 31, wid = tid >> 5;
    const int qtile = (gridDim.x - 1) - blockIdx.x;   // longest first
    const int bh = blockIdx.y;
    const int q0 = qtile * 128;
    const int m0 = wid * 16;
    const int r = lane >> 2, cq = lane & 3;

    const int eL = lane & 7;
    const uint32_t sK = smem_u32(KhB), sV = smem_u32(VhB);
    const uint32_t k_loff = ((8 * (lane >> 4) + eL) * SKH + 8 * ((lane >> 3) & 1)) * 2;
    const uint32_t v_loff = ((8 * ((lane >> 3) & 1) + eL) * SKH + 8 * (lane >> 4)) * 2;

    // Q fragments in registers (direct LDG, half)
    const __half* Qb = g_Qh + ((size_t)bh * T_ + q0 + m0) * D_;
    uint32_t qa[4][4];
#pragma unroll
    for (int t = 0; t < 4; t++) {
        qa[t][0] = *(const uint32_t*)(Qb + (r)     * D_ + 16 * t + 2 * cq);
        qa[t][1] = *(const uint32_t*)(Qb + (r + 8) * D_ + 16 * t + 2 * cq);
        qa[t][2] = *(const uint32_t*)(Qb + (r)     * D_ + 16 * t + 8 + 2 * cq);
        qa[t][3] = *(const uint32_t*)(Qb + (r + 8) * D_ + 16 * t + 8 + 2 * cq);
    }

    float o[8][4];
#pragma unroll
    for (int j = 0; j < 8; j++)
#pragma unroll
        for (int e = 0; e < 4; e++) o[j][e] = 0.f;
    float mr0 = -1e30f, mr1 = -1e30f, l0 = 0.f, l1 = 0.f;

    const __half* Kbh = g_Kh + (size_t)bh * T_ * D_;
    const __half* Vbh = g_Vh + (size_t)bh * T_ * D_;
    const int ntiles = (q0 + 128) / 64;

    // prologue: tiles 0, 1, 2
#pragma unroll
    for (int st = 0; st < 3; st++) {
        if (st < ntiles) {
#pragma unroll
            for (int u = 0; u < 2; u++) {
                int cch = tid + u * 256;
                int row = cch >> 3, col8 = (cch & 7) * 8;
                CPA16(sK + st * A_STG + (row * SKH + col8) * 2,
                      Kbh + (size_t)(st * 64 + row) * D_ + col8);
                CPA16(sV + st * A_STG + (row * SKH + col8) * 2,
                      Vbh + (size_t)(st * 64 + row) * D_ + col8);
            }
        }
        CP_COMMIT();
    }

    int cur = 0, nxt = 3;
    for (int kt = 0; kt < ntiles; kt++) {
        CP_WAIT2();
        __syncthreads();
        if (kt + 3 < ntiles) {
            const int s3 = (kt + 3) * 64;
#pragma unroll
            for (int u = 0; u < 2; u++) {
                int cch = tid + u * 256;
                int row = cch >> 3, col8 = (cch & 7) * 8;
                CPA16(sK + nxt * A_STG + (row * SKH + col8) * 2,
                      Kbh + (size_t)(s3 + row) * D_ + col8);
                CPA16(sV + nxt * A_STG + (row * SKH + col8) * 2,
                      Vbh + (size_t)(s3 + row) * D_ + col8);
            }
        }
        CP_COMMIT();

        const int s0 = kt * 64;
        const uint32_t kbuf = sK + cur * A_STG;
        const uint32_t vbuf = sV + cur * A_STG;

        if (s0 <= q0 + m0 + 15) {   // tile not fully masked for this warp
            float s[8][4];
#pragma unroll
            for (int j = 0; j < 8; j++)
#pragma unroll
                for (int e = 0; e < 4; e++) s[j][e] = 0.f;
#pragma unroll
            for (int t = 0; t < 4; t++) {
                uint32_t b[8][2];
#pragma unroll
                for (int q = 0; q < 4; q++)
                    LDSM4(b[2*q][0], b[2*q][1], b[2*q+1][0], b[2*q+1][1],
                          kbuf + k_loff + (q * 16 * SKH + t * 16) * 2);
#pragma unroll
                for (int j = 0; j < 8; j++)
                    mma_fp16(s[j], qa[t], b[j]);
            }

            const float sc = 0.125f;
            if (s0 + 63 > q0 + m0) {
                const int r0l = q0 + m0 + r, r1l = r0l + 8;
#pragma unroll
                for (int j = 0; j < 8; j++) {
                    const int col = s0 + j * 8 + 2 * cq;
                    s[j][0] = (col     <= r0l) ? s[j][0] * sc : -1e30f;
                    s[j][1] = (col + 1 <= r0l) ? s[j][1] * sc : -1e30f;
                    s[j][2] = (col     <= r1l) ? s[j][2] * sc : -1e30f;
                    s[j][3] = (col + 1 <= r1l) ? s[j][3] * sc : -1e30f;
                }
            } else {
#pragma unroll
                for (int j = 0; j < 8; j++)
#pragma unroll
                    for (int e = 0; e < 4; e++) s[j][e] *= sc;
            }

            float mx0 = -1e30f, mx1 = -1e30f;
#pragma unroll
            for (int j = 0; j < 8; j++) {
                mx0 = fmaxf(mx0, fmaxf(s[j][0], s[j][1]));
                mx1 = fmaxf(mx1, fmaxf(s[j][2], s[j][3]));
            }
            mx0 = fmaxf(mx0, __shfl_xor_sync(0xffffffffu, mx0, 1));
            mx0 = fmaxf(mx0, __shfl_xor_sync(0xffffffffu, mx0, 2));
            mx1 = fmaxf(mx1, __shfl_xor_sync(0xffffffffu, mx1, 1));
            mx1 = fmaxf(mx1, __shfl_xor_sync(0xffffffffu, mx1, 2));

            const float nm0 = fmaxf(mr0, mx0), nm1 = fmaxf(mr1, mx1);
            const float al0 = __expf(mr0 - nm0), al1 = __expf(mr1 - nm1);
            mr0 = nm0; mr1 = nm1;

            // exp via ex2.approx.f16x2: P = 2^((s - nm)*log2e), directly fp16
            const float L2E = 1.44269504f;
            const float nb0 = nm0 * L2E, nb1 = nm1 * L2E;
            uint32_t pfrag[4][4];
            float ls0 = 0.f, ls1 = 0.f;
#pragma unroll
            for (int j = 0; j < 8; j++) {
                uint32_t t01 = f2h2(fmaf(s[j][0], L2E, -nb0), fmaf(s[j][1], L2E, -nb0));
                uint32_t t23 = f2h2(fmaf(s[j][2], L2E, -nb1), fmaf(s[j][3], L2E, -nb1));
                uint32_t h01, h23;
                EX2_H2(h01, t01);
                EX2_H2(h23, t23);
                float2 f01 = __half22float2(*(__half2*)&h01);
                float2 f23 = __half22float2(*(__half2*)&h23);
                ls0 += f01.x + f01.y;
                ls1 += f23.x + f23.y;
                pfrag[j >> 1][(j & 1) * 2 + 0] = h01;
                pfrag[j >> 1][(j & 1) * 2 + 1] = h23;
            }
            ls0 += __shfl_xor_sync(0xffffffffu, ls0, 1);
            ls0 += __shfl_xor_sync(0xffffffffu, ls0, 2);
            ls1 += __shfl_xor_sync(0xffffffffu, ls1, 1);
            ls1 += __shfl_xor_sync(0xffffffffu, ls1, 2);
            l0 = l0 * al0 + ls0;
            l1 = l1 * al1 + ls1;

#pragma unroll
            for (int j = 0; j < 8; j++) {
                o[j][0] *= al0; o[j][1] *= al0;
                o[j][2] *= al1; o[j][3] *= al1;
            }

#pragma unroll
            for (int t = 0; t < 4; t++) {
                uint32_t b[8][2];
#pragma unroll
                for (int q = 0; q < 4; q++)
                    LDSM4T(b[2*q][0], b[2*q][1], b[2*q+1][0], b[2*q+1][1],
                           vbuf + v_loff + (t * 16 * SKH + q * 16) * 2);
#pragma unroll
                for (int j = 0; j < 8; j++)
                    mma_fp16(o[j], pfrag[t], b[j]);
            }
        }
        cur = (cur == 3) ? 0 : cur + 1;
        nxt = (nxt == 3) ? 0 : nxt + 1;
    }

    // Epilogue: normalize, write [B,T,C] half
    const int b = bh >> 4, h = bh & 15;
    const float inv0 = 1.f / l0, inv1 = 1.f / l1;
    const int t0 = q0 + m0 + r;
#pragma unroll
    for (int j = 0; j < 8; j++) {
        const int d = j * 8 + 2 * cq;
        *(uint32_t*)(g_Yh + ((size_t)b * T_ + t0)     * C_ + h * 64 + d)
            = f2h2(o[j][0] * inv0, o[j][1] * inv0);
        *(uint32_t*)(g_Yh + ((size_t)b * T_ + t0 + 8) * C_ + h * 64 + d)
            = f2h2(o[j][2] * inv1, o[j][3] * inv1);
    }
}

// ---------------------------------------------------------------------------
extern "C" void kernel_launch(void* const* d_in, const int* in_sizes, int n_in,
                              void* d_out, int out_size)
{
    const float* X  = (const float*)d_in[0];
    const float* Wq = (const float*)d_in[1];
    const float* Wk = (const float*)d_in[2];
    const float* Wv = (const float*)d_in[3];
    const float* Wo = (const float*)d_in[4];
    const float* bo = (const float*)d_in[5];
    float* out = (float*)d_out;

    cudaFuncSetAttribute(gemm_h, cudaFuncAttributeMaxDynamicSharedMemorySize, GEMM_SMEM);
    cudaFuncSetAttribute(attn_h, cudaFuncAttributeMaxDynamicSharedMemorySize, ATT_SMEM);

    const int ntotal = NXE + 4 * NWE;   // 12582912
    convert_all<<<ntotal / 1024, 256>>>(X, Wq, Wk, Wv, Wo);

    // QKV fused: gridDim.z selects weight/output
    gemm_h<<<dim3(NK_ / 128, M_ / 128, 3), 256, GEMM_SMEM>>>(nullptr, nullptr, 1);

    attn_h<<<dim3(T_ / 128, B_ * H_), 256, ATT_SMEM>>>();

    // O projection
    gemm_h<<<dim3(NK_ / 128, M_ / 128, 1), 256, GEMM_SMEM>>>(out, bo, 2);
}